// round 3
// baseline (speedup 1.0000x reference)
#include <cuda_runtime.h>
#include <cuda_bf16.h>
#include <math.h>
#include <stdint.h>

#define Bn 512
#define Vn 128
#define Dn 256
#define Hn 4
#define DHn 64

// ---------------- scratch (no cudaMalloc allowed) ----------------
__device__ float g_Wx[(size_t)Bn * Vn * Dn];   // 67 MB: Wx[b][v][d], d = h*64+d'
__device__ float g_ef[Vn * Vn * Hn];           // ef[i][j][h]
__device__ int   g_mask_mode;                  // 0=u8, 1=i32, 2=f32

// ---------------- mask dtype detection ----------------
__global__ void detect_mask_kernel(const unsigned int* __restrict__ m) {
    __shared__ int okInt, okFloat;
    if (threadIdx.x == 0) { okInt = 1; okFloat = 1; }
    __syncthreads();
    int badI = 0, badF = 0;
    // first 16384 u32 words = 65536 bytes: safe for all three candidate dtypes
    for (int idx = threadIdx.x; idx < 16384; idx += 256) {
        unsigned int v = m[idx];
        if (v > 1u) badI = 1;
        if (v != 0u && v != 0x3f800000u) badF = 1;
    }
    if (badI) okInt = 0;     // racy-but-idempotent zero writes
    if (badF) okFloat = 0;
    __syncthreads();
    if (threadIdx.x == 0) g_mask_mode = okFloat ? 2 : (okInt ? 1 : 0);
}

// ---------------- ef[i][j][h] = sum_e edge_attr[i][j][e] * Ew[h][e] ----------------
__global__ void ef_kernel(const float* __restrict__ ea, const float* __restrict__ Ew) {
    int idx = blockIdx.x * blockDim.x + threadIdx.x;  // 0..16383 = i*128+j
    if (idx >= Vn * Vn) return;
    float e0 = ea[idx * 2], e1 = ea[idx * 2 + 1];
    float4 o;
    o.x = e0 * Ew[0] + e1 * Ew[1];
    o.y = e0 * Ew[2] + e1 * Ew[3];
    o.z = e0 * Ew[4] + e1 * Ew[5];
    o.w = e0 * Ew[6] + e1 * Ew[7];
    ((float4*)g_ef)[idx] = o;
}

// ---------------- GEMM1: Wx[m][n] = sum_k x[m][k] * W[n][k] ----------------
// M = B*V = 65536, N = 256, K = 256. BM=128, BN=64, BK=16, 256 threads, 8x4 tile.
#define BM 128
#define BN 64
#define BK 16

__global__ __launch_bounds__(256) void gemm_wx_kernel(const float* __restrict__ x,
                                                      const float* __restrict__ W) {
    __shared__ float sA[BK][BM + 4];
    __shared__ float sB[BK][BN + 4];

    int m0 = blockIdx.x * BM;
    int n0 = blockIdx.y * BN;
    int t  = threadIdx.x;
    int ty = t >> 4;        // 0..15 -> rows ty*8..+7
    int tx = t & 15;        // 0..15 -> cols tx*4..+3

    float acc[8][4];
#pragma unroll
    for (int r = 0; r < 8; r++)
#pragma unroll
        for (int c = 0; c < 4; c++) acc[r][c] = 0.f;

    for (int k0 = 0; k0 < Dn; k0 += BK) {
        // load A tile: 128 rows x 16 k = 512 float4, 2 per thread
#pragma unroll
        for (int q = 0; q < 2; q++) {
            int f   = t * 2 + q;
            int row = f >> 2;
            int kq  = f & 3;
            float4 v = *(const float4*)(x + (size_t)(m0 + row) * Dn + k0 + kq * 4);
            sA[kq * 4 + 0][row] = v.x;
            sA[kq * 4 + 1][row] = v.y;
            sA[kq * 4 + 2][row] = v.z;
            sA[kq * 4 + 3][row] = v.w;
        }
        // load B tile: 64 rows(n) x 16 k = 256 float4, 1 per thread
        {
            int row = t >> 2;
            int kq  = t & 3;
            float4 v = *(const float4*)(W + (size_t)(n0 + row) * Dn + k0 + kq * 4);
            sB[kq * 4 + 0][row] = v.x;
            sB[kq * 4 + 1][row] = v.y;
            sB[kq * 4 + 2][row] = v.z;
            sB[kq * 4 + 3][row] = v.w;
        }
        __syncthreads();

#pragma unroll
        for (int k = 0; k < BK; k++) {
            float4 a0 = *(const float4*)&sA[k][ty * 8];
            float4 a1 = *(const float4*)&sA[k][ty * 8 + 4];
            float4 b0 = *(const float4*)&sB[k][tx * 4];
            float av[8] = {a0.x, a0.y, a0.z, a0.w, a1.x, a1.y, a1.z, a1.w};
            float bv[4] = {b0.x, b0.y, b0.z, b0.w};
#pragma unroll
            for (int r = 0; r < 8; r++)
#pragma unroll
                for (int c = 0; c < 4; c++) acc[r][c] += av[r] * bv[c];
        }
        __syncthreads();
    }

#pragma unroll
    for (int r = 0; r < 8; r++) {
        float4 o = make_float4(acc[r][0], acc[r][1], acc[r][2], acc[r][3]);
        *(float4*)(g_Wx + (size_t)(m0 + ty * 8 + r) * Dn + n0 + tx * 4) = o;
    }
}

// ---------------- fused attention per (b, h) ----------------
// dyn smem layout (floats):
//  [0)      sAlpha  16384      scores/probs [i][j], stride 128
//  [16384)  sWx     128*68     Wx tile [i][d'], stride 68 (pad, 16B-aligned rows)
//  [25088)  sAvec   128        a vector (a_src | a_dst)
//  [25216)  sMb     128        mask bias: 0 or -inf
//  [25344)  sSrc    128        s_src + bias
//  [25472)  sDst    128        s_dst + bias
//  [25600)  sMI     128        col max, then 1/denom
//  [25728)  sRed    256        reduction scratch
//  [25984)  sPS     256        partial s_src
//  [26240)  sPD     256        partial s_dst
#define ATT_SMEM_FLOATS 26496
#define WX_STRIDE 68

__global__ __launch_bounds__(256) void gat_attn_kernel(const int* __restrict__ adj,
                                                       const void* __restrict__ maskp,
                                                       const float* __restrict__ a,
                                                       float* __restrict__ out) {
    extern __shared__ float sm[];
    float* sAlpha = sm;
    float* sWx    = sm + 16384;
    float* sAvec  = sm + 25088;
    float* sMb    = sm + 25216;
    float* sSrc   = sm + 25344;
    float* sDst   = sm + 25472;
    float* sMI    = sm + 25600;
    float* sRed   = sm + 25728;
    float* sPS    = sm + 25984;
    float* sPD    = sm + 26240;

    int h = blockIdx.x;   // 0..3
    int b = blockIdx.y;   // 0..511
    int t = threadIdx.x;  // 0..255

    if (t < 128) {
        sAvec[t] = a[t];
        int mode = g_mask_mode;
        bool mv;
        int idx = b * Vn + t;
        if (mode == 0)      mv = ((const unsigned char*)maskp)[idx] != 0;
        else if (mode == 1) mv = ((const int*)maskp)[idx] != 0;
        else                mv = ((const float*)maskp)[idx] != 0.f;
        sMb[t] = mv ? -INFINITY : 0.f;
    }
    __syncthreads();

    // ---- load Wx[b, :, h, :] tile and compute s_src/s_dst partial dots ----
    {
        int i = t >> 1, half = t & 1;
        const float4* src =
            (const float4*)(g_Wx + (size_t)(b * Vn + i) * Dn + h * DHn + half * 32);
        float ss = 0.f, sd = 0.f;
#pragma unroll
        for (int q = 0; q < 8; q++) {
            float4 v = src[q];
            int d = half * 32 + q * 4;
            *(float4*)&sWx[i * WX_STRIDE + d] = v;
            ss += v.x * sAvec[d] + v.y * sAvec[d + 1] + v.z * sAvec[d + 2] + v.w * sAvec[d + 3];
            sd += v.x * sAvec[64 + d] + v.y * sAvec[64 + d + 1] +
                  v.z * sAvec[64 + d + 2] + v.w * sAvec[64 + d + 3];
        }
        sPS[t] = ss;
        sPD[t] = sd;
    }
    __syncthreads();
    if (t < 128) {
        sSrc[t] = sPS[2 * t] + sPS[2 * t + 1] + sMb[t];
        sDst[t] = sPD[2 * t] + sPD[2 * t + 1] + sMb[t];
    }
    __syncthreads();

    // ---- scores e[i][j] with leaky-relu + validity folded as -inf ----
    {
        int j = t & 127, half = t >> 7;
        int ibase = half * 64;
        float fdj  = sDst[j];
        float mloc = -INFINITY;
#pragma unroll 4
        for (int ii = 0; ii < 64; ii++) {
            int i  = ibase + ii;
            int av = adj[i * Vn + j];
            float ev = -INFINITY;
            if (av) {
                float s = sSrc[i] + fdj + g_ef[(i * Vn + j) * Hn + h];
                ev = (s >= 0.f) ? s : 0.2f * s;
            }
            sAlpha[i * Vn + j] = ev;
            mloc = fmaxf(mloc, ev);
        }
        sRed[t] = mloc;
    }
    __syncthreads();
    if (t < 128) {
        float m = fmaxf(sRed[t], sRed[t + 128]);
        if (!(m > -INFINITY)) m = 0.f;  // all-invalid column -> m = 0
        sMI[t] = m;
    }
    __syncthreads();

    // ---- exp + denom ----
    {
        int j = t & 127, half = t >> 7;
        int ibase = half * 64;
        float mj   = sMI[j];
        float dloc = 0.f;
#pragma unroll 4
        for (int ii = 0; ii < 64; ii++) {
            int i = ibase + ii;
            float p = expf(sAlpha[i * Vn + j] - mj);  // exp(-inf - m) = 0
            sAlpha[i * Vn + j] = p;
            dloc += p;
        }
        sRed[t] = dloc;
    }
    __syncthreads();
    if (t < 128) {
        float den = sRed[t] + sRed[t + 128];
        sMI[t] = 1.0f / ((den == 0.f) ? 1.f : den);
    }
    __syncthreads();

    // ---- aggregation: out[j][d] = (sum_i p[i][j] * Wx[i][d]) * inv_den[j] ----
    {
        int dg = t & 15;   // d = dg*4..+3
        int jg = t >> 4;   // j = jg*8..+7
        float acc[8][4];
#pragma unroll
        for (int r = 0; r < 8; r++)
#pragma unroll
            for (int c = 0; c < 4; c++) acc[r][c] = 0.f;

        for (int i = 0; i < 128; i++) {
            float4 wv = *(const float4*)&sWx[i * WX_STRIDE + dg * 4];
#pragma unroll
            for (int r = 0; r < 8; r++) {
                float al = sAlpha[i * Vn + jg * 8 + r];
                acc[r][0] += al * wv.x;
                acc[r][1] += al * wv.y;
                acc[r][2] += al * wv.z;
                acc[r][3] += al * wv.w;
            }
        }

#pragma unroll
        for (int r = 0; r < 8; r++) {
            int j = jg * 8 + r;
            float inv   = sMI[j];
            bool masked = (sMb[j] != 0.f);
            float v0 = acc[r][0] * inv;
            float v1 = acc[r][1] * inv;
            float v2 = acc[r][2] * inv;
            float v3 = acc[r][3] * inv;
            float4 o;
            o.x = masked ? 0.f : (v0 > 0.f ? v0 : expm1f(v0));
            o.y = masked ? 0.f : (v1 > 0.f ? v1 : expm1f(v1));
            o.z = masked ? 0.f : (v2 > 0.f ? v2 : expm1f(v2));
            o.w = masked ? 0.f : (v3 > 0.f ? v3 : expm1f(v3));
            *(float4*)(out + (size_t)(b * Vn + j) * Dn + h * DHn + dg * 4) = o;
        }
    }
}

// ---------------- launch ----------------
extern "C" void kernel_launch(void* const* d_in, const int* in_sizes, int n_in,
                              void* d_out, int out_size) {
    const float* x    = (const float*)d_in[0];  // (B,V,D)
    const int*   adj  = (const int*)d_in[1];    // (V,V)
    const float* ea   = (const float*)d_in[2];  // (V,V,E)
    const void*  mask = (const void*)d_in[3];   // (B,V) bool-ish
    const float* W    = (const float*)d_in[4];  // (D,D)
    const float* a    = (const float*)d_in[5];  // (2*Dh,)
    const float* Ew   = (const float*)d_in[6];  // (H,E)
    float* out = (float*)d_out;

    cudaFuncSetAttribute(gat_attn_kernel, cudaFuncAttributeMaxDynamicSharedMemorySize,
                         ATT_SMEM_FLOATS * sizeof(float));

    detect_mask_kernel<<<1, 256>>>((const unsigned int*)mask);
    ef_kernel<<<(Vn * Vn + 255) / 256, 256>>>(ea, Ew);
    gemm_wx_kernel<<<dim3((Bn * Vn) / BM, Dn / BN), 256>>>(x, W);
    gat_attn_kernel<<<dim3(Hn, Bn), 256, ATT_SMEM_FLOATS * sizeof(float)>>>(adj, mask, a, out);
}

// round 5
// speedup vs baseline: 1.3358x; 1.3358x over previous
#include <cuda_runtime.h>
#include <cuda_bf16.h>
#include <math.h>
#include <stdint.h>

#define Bn 512
#define Vn 128
#define Dn 256
#define Hn 4
#define DHn 64

// ---------------- scratch (no cudaMalloc allowed) ----------------
__device__ __nv_bfloat16 g_Wxh[(size_t)Bn * Vn * Dn];  // Wx hi bf16
__device__ __nv_bfloat16 g_Wxl[(size_t)Bn * Vn * Dn];  // Wx lo bf16 (residual)
__device__ float g_ef[Vn * Vn * Hn];                   // ef[i][j][h]
__device__ int   g_mask_mode;                          // 0=u8, 1=i32, 2=f32

// ---------------- helpers ----------------
__device__ __forceinline__ void mma_bf16(float* c, const uint32_t* a, uint32_t b0, uint32_t b1) {
    asm volatile(
        "mma.sync.aligned.m16n8k16.row.col.f32.bf16.bf16.f32 "
        "{%0,%1,%2,%3},{%4,%5,%6,%7},{%8,%9},{%0,%1,%2,%3};"
        : "+f"(c[0]), "+f"(c[1]), "+f"(c[2]), "+f"(c[3])
        : "r"(a[0]), "r"(a[1]), "r"(a[2]), "r"(a[3]), "r"(b0), "r"(b1));
}

// split two floats into packed hi-pair and lo-pair bf16x2
__device__ __forceinline__ void split2(float a, float b, uint32_t& hi, uint32_t& lo) {
    __nv_bfloat16 ha = __float2bfloat16_rn(a);
    __nv_bfloat16 hb = __float2bfloat16_rn(b);
    float ra = a - __bfloat162float(ha);
    float rb = b - __bfloat162float(hb);
    __nv_bfloat162 vh; vh.x = ha; vh.y = hb;
    __nv_bfloat162 vl; vl.x = __float2bfloat16_rn(ra); vl.y = __float2bfloat16_rn(rb);
    hi = *reinterpret_cast<uint32_t*>(&vh);
    lo = *reinterpret_cast<uint32_t*>(&vl);
}

// ---------------- mask dtype detection ----------------
__global__ void detect_mask_kernel(const unsigned int* __restrict__ m) {
    __shared__ int okInt, okFloat;
    if (threadIdx.x == 0) { okInt = 1; okFloat = 1; }
    __syncthreads();
    int badI = 0, badF = 0;
    for (int idx = threadIdx.x; idx < 16384; idx += 256) {
        unsigned int v = m[idx];
        if (v > 1u) badI = 1;
        if (v != 0u && v != 0x3f800000u) badF = 1;
    }
    if (badI) okInt = 0;
    if (badF) okFloat = 0;
    __syncthreads();
    if (threadIdx.x == 0) g_mask_mode = okFloat ? 2 : (okInt ? 1 : 0);
}

// ---------------- ef[i][j][h] = edge_attr[i][j][:] . Ew[h][:] ----------------
__global__ void ef_kernel(const float* __restrict__ ea, const float* __restrict__ Ew) {
    int idx = blockIdx.x * blockDim.x + threadIdx.x;
    if (idx >= Vn * Vn) return;
    float e0 = ea[idx * 2], e1 = ea[idx * 2 + 1];
    float4 o;
    o.x = e0 * Ew[0] + e1 * Ew[1];
    o.y = e0 * Ew[2] + e1 * Ew[3];
    o.z = e0 * Ew[4] + e1 * Ew[5];
    o.w = e0 * Ew[6] + e1 * Ew[7];
    ((float4*)g_ef)[idx] = o;
}

// ---------------- GEMM1: Wx[m][n] = sum_k x[m][k] * W[n][k], 3x-bf16 split ----------------
// M=65536, N=256, K=256. BM=128, BN=64, BK=32. 256 threads = 8 warps (4 x 2 layout).
#define G_BM 128
#define G_BN 64
#define G_BK 32
#define G_KP 40  // padded k stride (bf16 elems)

__global__ __launch_bounds__(256) void gemm_wx_kernel(const float* __restrict__ x,
                                                      const float* __restrict__ W) {
    __shared__ __nv_bfloat16 sAh[G_BM * G_KP];
    __shared__ __nv_bfloat16 sAl[G_BM * G_KP];
    __shared__ __nv_bfloat16 sBh[G_BN * G_KP];
    __shared__ __nv_bfloat16 sBl[G_BN * G_KP];

    int m0 = blockIdx.x * G_BM;
    int n0 = blockIdx.y * G_BN;
    int t = threadIdx.x;
    int w = t >> 5, lane = t & 31;
    int wm = w & 3;   // 0..3: 32 m-rows each
    int wn = w >> 2;  // 0..1: 32 n-cols each

    float acc[2][4][4];
#pragma unroll
    for (int mt = 0; mt < 2; mt++)
#pragma unroll
        for (int nt = 0; nt < 4; nt++)
#pragma unroll
            for (int r = 0; r < 4; r++) acc[mt][nt][r] = 0.f;

    for (int k0 = 0; k0 < Dn; k0 += G_BK) {
        // A tile: 128 x 32 fp32 -> hi/lo bf16
#pragma unroll
        for (int q = 0; q < 4; q++) {
            int idx = t + 256 * q;
            int row = idx >> 3;
            int kq = (idx & 7) * 4;
            float4 v = *(const float4*)(x + (size_t)(m0 + row) * Dn + k0 + kq);
            uint32_t h01, l01, h23, l23;
            split2(v.x, v.y, h01, l01);
            split2(v.z, v.w, h23, l23);
            *(uint32_t*)&sAh[row * G_KP + kq] = h01;
            *(uint32_t*)&sAh[row * G_KP + kq + 2] = h23;
            *(uint32_t*)&sAl[row * G_KP + kq] = l01;
            *(uint32_t*)&sAl[row * G_KP + kq + 2] = l23;
        }
        // B tile: 64 x 32
#pragma unroll
        for (int q = 0; q < 2; q++) {
            int idx = t + 256 * q;
            int row = idx >> 3;
            int kq = (idx & 7) * 4;
            float4 v = *(const float4*)(W + (size_t)(n0 + row) * Dn + k0 + kq);
            uint32_t h01, l01, h23, l23;
            split2(v.x, v.y, h01, l01);
            split2(v.z, v.w, h23, l23);
            *(uint32_t*)&sBh[row * G_KP + kq] = h01;
            *(uint32_t*)&sBh[row * G_KP + kq + 2] = h23;
            *(uint32_t*)&sBl[row * G_KP + kq] = l01;
            *(uint32_t*)&sBl[row * G_KP + kq + 2] = l23;
        }
        __syncthreads();

#pragma unroll
        for (int ks = 0; ks < G_BK; ks += 16) {
            uint32_t Ah[2][4], Al[2][4];
#pragma unroll
            for (int mt = 0; mt < 2; mt++)
#pragma unroll
                for (int r = 0; r < 4; r++) {
                    int row = wm * 32 + mt * 16 + (lane >> 2) + (r & 1) * 8;
                    int kk = ks + (lane & 3) * 2 + (r >> 1) * 8;
                    Ah[mt][r] = *(const uint32_t*)&sAh[row * G_KP + kk];
                    Al[mt][r] = *(const uint32_t*)&sAl[row * G_KP + kk];
                }
#pragma unroll
            for (int nt = 0; nt < 4; nt++) {
                int n = wn * 32 + nt * 8 + (lane >> 2);
                int kk = ks + (lane & 3) * 2;
                uint32_t bh0 = *(const uint32_t*)&sBh[n * G_KP + kk];
                uint32_t bh1 = *(const uint32_t*)&sBh[n * G_KP + kk + 8];
                uint32_t bl0 = *(const uint32_t*)&sBl[n * G_KP + kk];
                uint32_t bl1 = *(const uint32_t*)&sBl[n * G_KP + kk + 8];
#pragma unroll
                for (int mt = 0; mt < 2; mt++) {
                    mma_bf16(acc[mt][nt], Ah[mt], bh0, bh1);
                    mma_bf16(acc[mt][nt], Al[mt], bh0, bh1);
                    mma_bf16(acc[mt][nt], Ah[mt], bl0, bl1);
                }
            }
        }
        __syncthreads();
    }

    // epilogue: write Wx as hi/lo bf16 pairs
#pragma unroll
    for (int mt = 0; mt < 2; mt++)
#pragma unroll
        for (int nt = 0; nt < 4; nt++) {
            int row0 = m0 + wm * 32 + mt * 16 + (lane >> 2);
            int col = n0 + wn * 32 + nt * 8 + (lane & 3) * 2;
            uint32_t hi, lo;
            split2(acc[mt][nt][0], acc[mt][nt][1], hi, lo);
            *(uint32_t*)&g_Wxh[(size_t)row0 * Dn + col] = hi;
            *(uint32_t*)&g_Wxl[(size_t)row0 * Dn + col] = lo;
            split2(acc[mt][nt][2], acc[mt][nt][3], hi, lo);
            *(uint32_t*)&g_Wxh[(size_t)(row0 + 8) * Dn + col] = hi;
            *(uint32_t*)&g_Wxl[(size_t)(row0 + 8) * Dn + col] = lo;
        }
}

// ---------------- fused attention per (b, h) ----------------
// SMEM (bytes):
//  sPh [128][136] bf16 @ 0       (34816)  scores/probs transposed: sPh[j][i], hi part
//  sPl [128][136] bf16 @ 34816   (34816)  lo part
//  sWh [64][136]  bf16 @ 69632   (17408)  WxT[d][i] hi
//  sWl [64][136]  bf16 @ 87040   (17408)  WxT[d][i] lo
//  misc fp32 @ 104448            (5632)
#define ISTR 136
#define ATT_SMEM_BYTES 110080

__global__ __launch_bounds__(256) void gat_attn_kernel(const int* __restrict__ adj,
                                                       const void* __restrict__ maskp,
                                                       const float* __restrict__ a,
                                                       float* __restrict__ out) {
    extern __shared__ char smem[];
    __nv_bfloat16* sPh = (__nv_bfloat16*)smem;
    __nv_bfloat16* sPl = (__nv_bfloat16*)(smem + 34816);
    __nv_bfloat16* sWh = (__nv_bfloat16*)(smem + 69632);
    __nv_bfloat16* sWl = (__nv_bfloat16*)(smem + 87040);
    float* sAvec = (float*)(smem + 104448);  // 128
    float* sMb = sAvec + 128;                // 128
    float* sSrc = sAvec + 256;               // 128
    float* sDst = sAvec + 384;               // 128
    float* sMI = sAvec + 512;                // 128
    float* sRed = sAvec + 640;               // 256
    float* sPS = sAvec + 896;                // 256
    float* sPD = sAvec + 1152;               // 256

    int h = blockIdx.x;
    int b = blockIdx.y;
    int t = threadIdx.x;

    if (t < 128) {
        sAvec[t] = a[t];
        int mode = g_mask_mode;
        bool mv;
        int idx = b * Vn + t;
        if (mode == 0)      mv = ((const unsigned char*)maskp)[idx] != 0;
        else if (mode == 1) mv = ((const int*)maskp)[idx] != 0;
        else                mv = ((const float*)maskp)[idx] != 0.f;
        sMb[t] = mv ? -INFINITY : 0.f;
    }
    __syncthreads();

    // ---- load Wx[b,:,h,:] (hi/lo), transpose into sWh/sWl[d][i], partial dots ----
    {
        int i = t >> 1, half = t & 1;
        size_t base = (size_t)(b * Vn + i) * Dn + h * DHn + half * 32;
        const __nv_bfloat162* ph = (const __nv_bfloat162*)(g_Wxh + base);
        const __nv_bfloat162* pl = (const __nv_bfloat162*)(g_Wxl + base);
        float ss = 0.f, sd = 0.f;
#pragma unroll
        for (int q = 0; q < 16; q++) {
            __nv_bfloat162 vh = ph[q];
            __nv_bfloat162 vl = pl[q];
            int d = half * 32 + q * 2;
            float f0 = __bfloat162float(vh.x) + __bfloat162float(vl.x);
            float f1 = __bfloat162float(vh.y) + __bfloat162float(vl.y);
            sWh[d * ISTR + i] = vh.x;
            sWh[(d + 1) * ISTR + i] = vh.y;
            sWl[d * ISTR + i] = vl.x;
            sWl[(d + 1) * ISTR + i] = vl.y;
            ss += f0 * sAvec[d] + f1 * sAvec[d + 1];
            sd += f0 * sAvec[64 + d] + f1 * sAvec[64 + d + 1];
        }
        sPS[t] = ss;
        sPD[t] = sd;
    }
    __syncthreads();
    if (t < 128) {
        sSrc[t] = sPS[2 * t] + sPS[2 * t + 1] + sMb[t];
        sDst[t] = sPD[2 * t] + sPD[2 * t + 1] + sMb[t];
    }
    __syncthreads();

    // ---- scores e[i][j] (leaky-relu, -inf fold), stored transposed hi/lo ----
    {
        int j = t & 127, half = t >> 7;
        int ibase = half * 64;
        float fdj = sDst[j];
        float mloc = -INFINITY;
#pragma unroll 2
        for (int ii = 0; ii < 64; ii += 2) {
            int i0 = ibase + ii;
            float ev0 = -INFINITY, ev1 = -INFINITY;
            if (adj[i0 * Vn + j]) {
                float s = sSrc[i0] + fdj + g_ef[(i0 * Vn + j) * Hn + h];
                ev0 = (s >= 0.f) ? s : 0.2f * s;
            }
            if (adj[(i0 + 1) * Vn + j]) {
                float s = sSrc[i0 + 1] + fdj + g_ef[((i0 + 1) * Vn + j) * Hn + h];
                ev1 = (s >= 0.f) ? s : 0.2f * s;
            }
            mloc = fmaxf(mloc, fmaxf(ev0, ev1));
            __nv_bfloat16 h0 = __float2bfloat16_rn(ev0);
            __nv_bfloat16 h1 = __float2bfloat16_rn(ev1);
            float r0 = isfinite(ev0) ? ev0 - __bfloat162float(h0) : 0.f;
            float r1 = isfinite(ev1) ? ev1 - __bfloat162float(h1) : 0.f;
            __nv_bfloat162 vh; vh.x = h0; vh.y = h1;
            __nv_bfloat162 vl; vl.x = __float2bfloat16_rn(r0); vl.y = __float2bfloat16_rn(r1);
            *(uint32_t*)&sPh[j * ISTR + i0] = *(uint32_t*)&vh;
            *(uint32_t*)&sPl[j * ISTR + i0] = *(uint32_t*)&vl;
        }
        sRed[t] = mloc;
    }
    __syncthreads();
    if (t < 128) {
        float m = fmaxf(sRed[t], sRed[t + 128]);
        if (!(m > -INFINITY)) m = 0.f;
        sMI[t] = m;
    }
    __syncthreads();

    // ---- exp + denom; probs stored back hi/lo ----
    {
        int j = t & 127, half = t >> 7;
        int ibase = half * 64;
        float mj = sMI[j];
        float dloc = 0.f;
#pragma unroll 2
        for (int ii = 0; ii < 64; ii += 2) {
            int i0 = ibase + ii;
            uint32_t uh = *(uint32_t*)&sPh[j * ISTR + i0];
            uint32_t ul = *(uint32_t*)&sPl[j * ISTR + i0];
            __nv_bfloat162 vh = *(__nv_bfloat162*)&uh;
            __nv_bfloat162 vl = *(__nv_bfloat162*)&ul;
            float e0 = __bfloat162float(vh.x) + __bfloat162float(vl.x);
            float e1 = __bfloat162float(vh.y) + __bfloat162float(vl.y);
            float p0 = __expf(e0 - mj);
            float p1 = __expf(e1 - mj);
            dloc += p0 + p1;
            uint32_t hi, lo;
            split2(p0, p1, hi, lo);
            *(uint32_t*)&sPh[j * ISTR + i0] = hi;
            *(uint32_t*)&sPl[j * ISTR + i0] = lo;
        }
        sRed[t] = dloc;
    }
    __syncthreads();
    if (t < 128) {
        float den = sRed[t] + sRed[t + 128];
        sMI[t] = 1.0f / ((den == 0.f) ? 1.f : den);
    }
    __syncthreads();

    // ---- aggregation via 3x-bf16 mma: C[j][d] = sum_i P[j][i] * WxT[d][i] ----
    {
        int w = t >> 5, lane = t & 31;
        int rowA = w * 16 + (lane >> 2);
        int kl = (lane & 3) * 2;
        float acc[8][4];
#pragma unroll
        for (int nt = 0; nt < 8; nt++)
#pragma unroll
            for (int r = 0; r < 4; r++) acc[nt][r] = 0.f;

#pragma unroll
        for (int k0 = 0; k0 < 128; k0 += 16) {
            uint32_t Ah[4], Al[4];
#pragma unroll
            for (int r = 0; r < 4; r++) {
                int rr = rowA + (r & 1) * 8;
                int kk = k0 + kl + (r >> 1) * 8;
                Ah[r] = *(const uint32_t*)&sPh[rr * ISTR + kk];
                Al[r] = *(const uint32_t*)&sPl[rr * ISTR + kk];
            }
#pragma unroll
            for (int nt = 0; nt < 8; nt++) {
                int n = nt * 8 + (lane >> 2);
                uint32_t bh0 = *(const uint32_t*)&sWh[n * ISTR + k0 + kl];
                uint32_t bh1 = *(const uint32_t*)&sWh[n * ISTR + k0 + kl + 8];
                uint32_t bl0 = *(const uint32_t*)&sWl[n * ISTR + k0 + kl];
                uint32_t bl1 = *(const uint32_t*)&sWl[n * ISTR + k0 + kl + 8];
                mma_bf16(acc[nt], Ah, bh0, bh1);
                mma_bf16(acc[nt], Al, bh0, bh1);
                mma_bf16(acc[nt], Ah, bl0, bl1);
            }
        }

        // epilogue: normalize, ELU, mask, store
#pragma unroll
        for (int nt = 0; nt < 8; nt++) {
            int dd = nt * 8 + (lane & 3) * 2;
#pragma unroll
            for (int rh = 0; rh < 2; rh++) {
                int j = rowA + rh * 8;
                float inv = sMI[j];
                bool msk = (sMb[j] != 0.f);
                float v0 = acc[nt][rh * 2] * inv;
                float v1 = acc[nt][rh * 2 + 1] * inv;
                float2 o;
                o.x = msk ? 0.f : (v0 > 0.f ? v0 : expm1f(v0));
                o.y = msk ? 0.f : (v1 > 0.f ? v1 : expm1f(v1));
                *(float2*)(out + (size_t)(b * Vn + j) * Dn + h * DHn + dd) = o;
            }
        }
    }
}

// ---------------- launch ----------------
extern "C" void kernel_launch(void* const* d_in, const int* in_sizes, int n_in,
                              void* d_out, int out_size) {
    const float* x    = (const float*)d_in[0];
    const int*   adj  = (const int*)d_in[1];
    const float* ea   = (const float*)d_in[2];
    const void*  mask = (const void*)d_in[3];
    const float* W    = (const float*)d_in[4];
    const float* a    = (const float*)d_in[5];
    const float* Ew   = (const float*)d_in[6];
    float* out = (float*)d_out;

    cudaFuncSetAttribute(gat_attn_kernel, cudaFuncAttributeMaxDynamicSharedMemorySize,
                         ATT_SMEM_BYTES);

    detect_mask_kernel<<<1, 256>>>((const unsigned int*)mask);
    ef_kernel<<<(Vn * Vn + 255) / 256, 256>>>(ea, Ew);
    gemm_wx_kernel<<<dim3((Bn * Vn) / G_BM, Dn / G_BN), 256>>>(x, W);
    gat_attn_kernel<<<dim3(Hn, Bn), 256, ATT_SMEM_BYTES>>>(adj, mask, a, out);
}

// round 6
// speedup vs baseline: 1.4298x; 1.0704x over previous
#include <cuda_runtime.h>
#include <cuda_bf16.h>
#include <math.h>
#include <stdint.h>

#define Bn 512
#define Vn 128
#define Dn 256
#define Hn 4
#define DHn 64

// ---------------- scratch (no cudaMalloc allowed) ----------------
__device__ __nv_bfloat16 g_xh[(size_t)Bn * Vn * Dn];   // x hi bf16
__device__ __nv_bfloat16 g_xl[(size_t)Bn * Vn * Dn];   // x lo bf16
__device__ __nv_bfloat16 g_Wh[Dn * Dn];                // W hi
__device__ __nv_bfloat16 g_Wl[Dn * Dn];                // W lo
__device__ __nv_bfloat16 g_Wxh[(size_t)Bn * Vn * Dn];  // Wx hi
__device__ __nv_bfloat16 g_Wxl[(size_t)Bn * Vn * Dn];  // Wx lo
__device__ float g_efm[Hn * Vn * Vn];                  // [h][i][j] = adj? ef : -1e30
__device__ int   g_mask_mode;                          // 0=u8, 1=i32, 2=f32

#define NEGBIG (-1e30f)

// ---------------- helpers ----------------
__device__ __forceinline__ void mma_bf16(float* c, const uint32_t* a, uint32_t b0, uint32_t b1) {
    asm volatile(
        "mma.sync.aligned.m16n8k16.row.col.f32.bf16.bf16.f32 "
        "{%0,%1,%2,%3},{%4,%5,%6,%7},{%8,%9},{%0,%1,%2,%3};"
        : "+f"(c[0]), "+f"(c[1]), "+f"(c[2]), "+f"(c[3])
        : "r"(a[0]), "r"(a[1]), "r"(a[2]), "r"(a[3]), "r"(b0), "r"(b1));
}

__device__ __forceinline__ void ldsm_x4(uint32_t& r0, uint32_t& r1, uint32_t& r2, uint32_t& r3,
                                        uint32_t addr) {
    asm volatile("ldmatrix.sync.aligned.m8n8.x4.shared.b16 {%0,%1,%2,%3}, [%4];"
                 : "=r"(r0), "=r"(r1), "=r"(r2), "=r"(r3) : "r"(addr));
}
__device__ __forceinline__ void ldsm_x4_t(uint32_t& r0, uint32_t& r1, uint32_t& r2, uint32_t& r3,
                                          uint32_t addr) {
    asm volatile("ldmatrix.sync.aligned.m8n8.x4.trans.shared.b16 {%0,%1,%2,%3}, [%4];"
                 : "=r"(r0), "=r"(r1), "=r"(r2), "=r"(r3) : "r"(addr));
}
__device__ __forceinline__ uint32_t sptr(const void* p) {
    return (uint32_t)__cvta_generic_to_shared(p);
}

// split two floats into packed hi-pair and lo-pair bf16x2
__device__ __forceinline__ void split2(float a, float b, uint32_t& hi, uint32_t& lo) {
    __nv_bfloat16 ha = __float2bfloat16_rn(a);
    __nv_bfloat16 hb = __float2bfloat16_rn(b);
    float ra = a - __bfloat162float(ha);
    float rb = b - __bfloat162float(hb);
    __nv_bfloat162 vh; vh.x = ha; vh.y = hb;
    __nv_bfloat162 vl; vl.x = __float2bfloat16_rn(ra); vl.y = __float2bfloat16_rn(rb);
    hi = *reinterpret_cast<uint32_t*>(&vh);
    lo = *reinterpret_cast<uint32_t*>(&vl);
}

// ---------------- mask dtype detection ----------------
__global__ void detect_mask_kernel(const unsigned int* __restrict__ m) {
    __shared__ int okInt, okFloat;
    if (threadIdx.x == 0) { okInt = 1; okFloat = 1; }
    __syncthreads();
    int badI = 0, badF = 0;
    for (int idx = threadIdx.x; idx < 16384; idx += 256) {
        unsigned int v = m[idx];
        if (v > 1u) badI = 1;
        if (v != 0u && v != 0x3f800000u) badF = 1;
    }
    if (badI) okInt = 0;
    if (badF) okFloat = 0;
    __syncthreads();
    if (threadIdx.x == 0) g_mask_mode = okFloat ? 2 : (okInt ? 1 : 0);
}

// ---------------- converts ----------------
__global__ __launch_bounds__(256) void convert_x_kernel(const float* __restrict__ x) {
    int gid = blockIdx.x * 256 + threadIdx.x;  // one float4 each
    float4 v = ((const float4*)x)[gid];
    uint32_t h01, l01, h23, l23;
    split2(v.x, v.y, h01, l01);
    split2(v.z, v.w, h23, l23);
    ((uint2*)g_xh)[gid] = make_uint2(h01, h23);
    ((uint2*)g_xl)[gid] = make_uint2(l01, l23);
}

__global__ __launch_bounds__(256) void convert_w_kernel(const float* __restrict__ W) {
    int gid = blockIdx.x * 256 + threadIdx.x;  // 16384 float4
    float4 v = ((const float4*)W)[gid];
    uint32_t h01, l01, h23, l23;
    split2(v.x, v.y, h01, l01);
    split2(v.z, v.w, h23, l23);
    ((uint2*)g_Wh)[gid] = make_uint2(h01, h23);
    ((uint2*)g_Wl)[gid] = make_uint2(l01, l23);
}

// ---------------- efm[h][i][j] = adj[i][j] ? ea[i][j]·Ew[h] : -1e30 ----------------
__global__ void ef_kernel(const float* __restrict__ ea, const float* __restrict__ Ew,
                          const int* __restrict__ adj) {
    int idx = blockIdx.x * blockDim.x + threadIdx.x;  // i*128+j
    if (idx >= Vn * Vn) return;
    float e0 = ea[idx * 2], e1 = ea[idx * 2 + 1];
    bool ok = adj[idx] != 0;
    g_efm[0 * 16384 + idx] = ok ? (e0 * Ew[0] + e1 * Ew[1]) : NEGBIG;
    g_efm[1 * 16384 + idx] = ok ? (e0 * Ew[2] + e1 * Ew[3]) : NEGBIG;
    g_efm[2 * 16384 + idx] = ok ? (e0 * Ew[4] + e1 * Ew[5]) : NEGBIG;
    g_efm[3 * 16384 + idx] = ok ? (e0 * Ew[6] + e1 * Ew[7]) : NEGBIG;
}

// ---------------- GEMM1: Wx = x @ W^T (3x bf16 split, ldmatrix) ----------------
#define G_BM 128
#define G_BN 64
#define G_BK 32
#define G_KP 40  // padded k stride (bf16): 20 words -> conflict-free ldmatrix

__global__ __launch_bounds__(256) void gemm_wx_kernel() {
    __shared__ __nv_bfloat16 sAh[G_BM * G_KP];
    __shared__ __nv_bfloat16 sAl[G_BM * G_KP];
    __shared__ __nv_bfloat16 sBh[G_BN * G_KP];
    __shared__ __nv_bfloat16 sBl[G_BN * G_KP];

    int m0 = blockIdx.x * G_BM;
    int n0 = blockIdx.y * G_BN;
    int t = threadIdx.x;
    int w = t >> 5, lane = t & 31;
    int wm = w & 3;   // 32 m-rows
    int wn = w >> 2;  // 32 n-cols

    const uint32_t* gxh = (const uint32_t*)g_xh;
    const uint32_t* gxl = (const uint32_t*)g_xl;
    const uint32_t* gwh = (const uint32_t*)g_Wh;
    const uint32_t* gwl = (const uint32_t*)g_Wl;
    uint32_t* sAh32 = (uint32_t*)sAh;
    uint32_t* sAl32 = (uint32_t*)sAl;
    uint32_t* sBh32 = (uint32_t*)sBh;
    uint32_t* sBl32 = (uint32_t*)sBl;

    // per-lane ldmatrix address offsets
    int rowoffA = ((lane >> 3) & 1) * 8 + (lane & 7);  // A (non-trans, a-order)
    int coloffA = (lane >> 4) * 8;
    int rowoffB = (lane >> 4) * 8 + (lane & 7);        // B (non-trans, b-order)
    int coloffB = ((lane >> 3) & 1) * 8;

    uint32_t aAh = sptr(sAh), aAl = sptr(sAl), aBh = sptr(sBh), aBl = sptr(sBl);

    float acc[2][4][4];
#pragma unroll
    for (int mt = 0; mt < 2; mt++)
#pragma unroll
        for (int nt = 0; nt < 4; nt++)
#pragma unroll
            for (int r = 0; r < 4; r++) acc[mt][nt][r] = 0.f;

    for (int k0 = 0; k0 < Dn; k0 += G_BK) {
        // A: 128 rows x 16 u32 per array
#pragma unroll
        for (int q = 0; q < 8; q++) {
            int lin = t + 256 * q;
            int row = lin >> 4, cw = lin & 15;
            size_t src = (size_t)(m0 + row) * (Dn / 2) + (k0 >> 1) + cw;
            sAh32[row * (G_KP / 2) + cw] = gxh[src];
            sAl32[row * (G_KP / 2) + cw] = gxl[src];
        }
        // B: 64 rows x 16 u32 per array
#pragma unroll
        for (int q = 0; q < 4; q++) {
            int lin = t + 256 * q;
            int row = lin >> 4, cw = lin & 15;
            size_t src = (size_t)(n0 + row) * (Dn / 2) + (k0 >> 1) + cw;
            sBh32[row * (G_KP / 2) + cw] = gwh[src];
            sBl32[row * (G_KP / 2) + cw] = gwl[src];
        }
        __syncthreads();

#pragma unroll
        for (int ks = 0; ks < G_BK; ks += 16) {
            uint32_t Ah[2][4], Al[2][4];
#pragma unroll
            for (int mt = 0; mt < 2; mt++) {
                uint32_t off = ((wm * 32 + mt * 16 + rowoffA) * G_KP + ks + coloffA) * 2;
                ldsm_x4(Ah[mt][0], Ah[mt][1], Ah[mt][2], Ah[mt][3], aAh + off);
                ldsm_x4(Al[mt][0], Al[mt][1], Al[mt][2], Al[mt][3], aAl + off);
            }
#pragma unroll
            for (int nc = 0; nc < 2; nc++) {
                uint32_t off = ((wn * 32 + nc * 16 + rowoffB) * G_KP + ks + coloffB) * 2;
                uint32_t bh0, bh1, bh2, bh3, bl0, bl1, bl2, bl3;
                ldsm_x4(bh0, bh1, bh2, bh3, aBh + off);
                ldsm_x4(bl0, bl1, bl2, bl3, aBl + off);
#pragma unroll
                for (int mt = 0; mt < 2; mt++) {
                    mma_bf16(acc[mt][nc * 2], Ah[mt], bh0, bh1);
                    mma_bf16(acc[mt][nc * 2], Al[mt], bh0, bh1);
                    mma_bf16(acc[mt][nc * 2], Ah[mt], bl0, bl1);
                    mma_bf16(acc[mt][nc * 2 + 1], Ah[mt], bh2, bh3);
                    mma_bf16(acc[mt][nc * 2 + 1], Al[mt], bh2, bh3);
                    mma_bf16(acc[mt][nc * 2 + 1], Ah[mt], bl2, bl3);
                }
            }
        }
        __syncthreads();
    }

#pragma unroll
    for (int mt = 0; mt < 2; mt++)
#pragma unroll
        for (int nt = 0; nt < 4; nt++) {
            int row0 = m0 + wm * 32 + mt * 16 + (lane >> 2);
            int col = n0 + wn * 32 + nt * 8 + (lane & 3) * 2;
            uint32_t hi, lo;
            split2(acc[mt][nt][0], acc[mt][nt][1], hi, lo);
            *(uint32_t*)&g_Wxh[(size_t)row0 * Dn + col] = hi;
            *(uint32_t*)&g_Wxl[(size_t)row0 * Dn + col] = lo;
            split2(acc[mt][nt][2], acc[mt][nt][3], hi, lo);
            *(uint32_t*)&g_Wxh[(size_t)(row0 + 8) * Dn + col] = hi;
            *(uint32_t*)&g_Wxl[(size_t)(row0 + 8) * Dn + col] = lo;
        }
}

// ---------------- fused attention per (b, h) ----------------
#define ISTR 136  // P row stride (bf16): 68 words -> conflict-free ldmatrix
#define WSTR 72   // W row stride (bf16): 36 words -> conflict-free ldmatrix
// SMEM: sPh 34816 | sPl 34816 | sWh 18432 | sWl 18432 | misc 5632 = 112128 B
#define ATT_SMEM_BYTES 112128

__global__ __launch_bounds__(256) void gat_attn_kernel(const void* __restrict__ maskp,
                                                       const float* __restrict__ a,
                                                       float* __restrict__ out) {
    extern __shared__ char smem[];
    __nv_bfloat16* sPh = (__nv_bfloat16*)smem;
    __nv_bfloat16* sPl = (__nv_bfloat16*)(smem + 34816);
    __nv_bfloat16* sWh = (__nv_bfloat16*)(smem + 69632);
    __nv_bfloat16* sWl = (__nv_bfloat16*)(smem + 88064);
    float* sAvec = (float*)(smem + 106496);  // 128
    float* sMb = sAvec + 128;
    float* sSrc = sAvec + 256;
    float* sDst = sAvec + 384;
    float* sMI = sAvec + 512;
    float* sRed = sAvec + 640;  // 256
    float* sPS = sAvec + 896;   // 256
    float* sPD = sAvec + 1152;  // 256

    int h = blockIdx.x;
    int b = blockIdx.y;
    int t = threadIdx.x;

    if (t < 128) {
        sAvec[t] = a[t];
        int mode = g_mask_mode;
        bool mv;
        int idx = b * Vn + t;
        if (mode == 0)      mv = ((const unsigned char*)maskp)[idx] != 0;
        else if (mode == 1) mv = ((const int*)maskp)[idx] != 0;
        else                mv = ((const float*)maskp)[idx] != 0.f;
        sMb[t] = mv ? NEGBIG : 0.f;
    }
    __syncthreads();

    // ---- load Wx[b,:,h,:] hi/lo into sW [i][d] (no transpose) + partial dots ----
    {
        int i = t >> 1, half = t & 1;
        size_t base = ((size_t)(b * Vn + i) * Dn + h * DHn) >> 1;  // u32 units
        const uint32_t* ph = (const uint32_t*)g_Wxh + base + half * 16;
        const uint32_t* pl = (const uint32_t*)g_Wxl + base + half * 16;
        uint32_t* wh32 = (uint32_t*)sWh;
        uint32_t* wl32 = (uint32_t*)sWl;
        float ss = 0.f, sd = 0.f;
#pragma unroll
        for (int q = 0; q < 16; q++) {
            uint32_t uh = ph[q], ul = pl[q];
            int d = half * 32 + q * 2;
            wh32[i * (WSTR / 2) + (d >> 1)] = uh;
            wl32[i * (WSTR / 2) + (d >> 1)] = ul;
            float2 fh = __bfloat1622float2(*(__nv_bfloat162*)&uh);
            float2 fl = __bfloat1622float2(*(__nv_bfloat162*)&ul);
            float f0 = fh.x + fl.x, f1 = fh.y + fl.y;
            ss += f0 * sAvec[d] + f1 * sAvec[d + 1];
            sd += f0 * sAvec[64 + d] + f1 * sAvec[64 + d + 1];
        }
        sPS[t] = ss;
        sPD[t] = sd;
    }
    __syncthreads();
    if (t < 128) {
        sSrc[t] = sPS[2 * t] + sPS[2 * t + 1] + sMb[t];
        sDst[t] = sPD[2 * t] + sPD[2 * t + 1] + sMb[t];
    }
    __syncthreads();

    // ---- pass 1: column max only (no stores) ----
    const float* efb = g_efm + h * (Vn * Vn);
    {
        int j = t & 127, half = t >> 7;
        int ibase = half * 64;
        float fdj = sDst[j];
        float mloc = NEGBIG;
#pragma unroll 4
        for (int ii = 0; ii < 64; ii++) {
            int i = ibase + ii;
            float s = sSrc[i] + fdj + efb[i * Vn + j];
            float e = (s >= 0.f) ? s : 0.2f * s;
            mloc = fmaxf(mloc, e);
        }
        sRed[t] = mloc;
    }
    __syncthreads();
    if (t < 128) sMI[t] = fmaxf(sRed[t], sRed[t + 128]);
    __syncthreads();

    // ---- pass 2: recompute e, p = exp(e - m), store hi/lo packed, accumulate denom ----
    {
        int j = t & 127, half = t >> 7;
        int ibase = half * 64;
        float fdj = sDst[j];
        float mj = sMI[j];
        float dloc = 0.f;
        uint32_t* ph32 = (uint32_t*)sPh;
        uint32_t* pl32 = (uint32_t*)sPl;
#pragma unroll 2
        for (int ii = 0; ii < 64; ii += 2) {
            int i0 = ibase + ii;
            float s0 = sSrc[i0] + fdj + efb[i0 * Vn + j];
            float s1 = sSrc[i0 + 1] + fdj + efb[(i0 + 1) * Vn + j];
            float e0 = (s0 >= 0.f) ? s0 : 0.2f * s0;
            float e1 = (s1 >= 0.f) ? s1 : 0.2f * s1;
            float p0 = __expf(e0 - mj);
            float p1 = __expf(e1 - mj);
            dloc += p0 + p1;
            uint32_t hi, lo;
            split2(p0, p1, hi, lo);
            ph32[j * (ISTR / 2) + (i0 >> 1)] = hi;
            pl32[j * (ISTR / 2) + (i0 >> 1)] = lo;
        }
        sRed[t] = dloc;
    }
    __syncthreads();
    if (t < 128) {
        float den = sRed[t] + sRed[t + 128];
        sMI[t] = 1.0f / ((den == 0.f) ? 1.f : den);
    }
    __syncthreads();

    // ---- aggregation: C[j][d] = sum_i P[j][i] * Wx[i][d] via ldmatrix + mma ----
    {
        int w = t >> 5, lane = t & 31;
        int j0 = w * 16;
        int rowoffA = ((lane >> 3) & 1) * 8 + (lane & 7);  // A non-trans
        int coloffA = (lane >> 4) * 8;
        int rowoffBt = ((lane >> 3) & 1) * 8 + (lane & 7);  // B trans (rows = k)
        int coloffBt = (lane >> 4) * 8;

        uint32_t aPh = sptr(sPh), aPl = sptr(sPl), aWh = sptr(sWh), aWl = sptr(sWl);
        uint32_t offA = ((j0 + rowoffA) * ISTR + coloffA) * 2;

        float acc[8][4];
#pragma unroll
        for (int nt = 0; nt < 8; nt++)
#pragma unroll
            for (int r = 0; r < 4; r++) acc[nt][r] = 0.f;

#pragma unroll
        for (int k0 = 0; k0 < 128; k0 += 16) {
            uint32_t Ah[4], Al[4];
            ldsm_x4(Ah[0], Ah[1], Ah[2], Ah[3], aPh + offA + k0 * 2);
            ldsm_x4(Al[0], Al[1], Al[2], Al[3], aPl + offA + k0 * 2);
#pragma unroll
            for (int nc = 0; nc < 4; nc++) {
                uint32_t offB = ((k0 + rowoffBt) * WSTR + nc * 16 + coloffBt) * 2;
                uint32_t bh0, bh1, bh2, bh3, bl0, bl1, bl2, bl3;
                ldsm_x4_t(bh0, bh1, bh2, bh3, aWh + offB);
                ldsm_x4_t(bl0, bl1, bl2, bl3, aWl + offB);
                mma_bf16(acc[nc * 2], Ah, bh0, bh1);
                mma_bf16(acc[nc * 2], Al, bh0, bh1);
                mma_bf16(acc[nc * 2], Ah, bl0, bl1);
                mma_bf16(acc[nc * 2 + 1], Ah, bh2, bh3);
                mma_bf16(acc[nc * 2 + 1], Al, bh2, bh3);
                mma_bf16(acc[nc * 2 + 1], Ah, bl2, bl3);
            }
        }

        // epilogue: normalize, ELU, mask, store
        int rowA = j0 + (lane >> 2);
#pragma unroll
        for (int nt = 0; nt < 8; nt++) {
            int dd = nt * 8 + (lane & 3) * 2;
#pragma unroll
            for (int rh = 0; rh < 2; rh++) {
                int j = rowA + rh * 8;
                float inv = sMI[j];
                bool msk = (sMb[j] != 0.f);
                float v0 = acc[nt][rh * 2] * inv;
                float v1 = acc[nt][rh * 2 + 1] * inv;
                float2 o;
                o.x = msk ? 0.f : (v0 > 0.f ? v0 : expm1f(v0));
                o.y = msk ? 0.f : (v1 > 0.f ? v1 : expm1f(v1));
                *(float2*)(out + (size_t)(b * Vn + j) * Dn + h * DHn + dd) = o;
            }
        }
    }
}

// ---------------- launch ----------------
extern "C" void kernel_launch(void* const* d_in, const int* in_sizes, int n_in,
                              void* d_out, int out_size) {
    const float* x    = (const float*)d_in[0];
    const int*   adj  = (const int*)d_in[1];
    const float* ea   = (const float*)d_in[2];
    const void*  mask = (const void*)d_in[3];
    const float* W    = (const float*)d_in[4];
    const float* a    = (const float*)d_in[5];
    const float* Ew   = (const float*)d_in[6];
    float* out = (float*)d_out;

    cudaFuncSetAttribute(gat_attn_kernel, cudaFuncAttributeMaxDynamicSharedMemorySize,
                         ATT_SMEM_BYTES);

    detect_mask_kernel<<<1, 256>>>((const unsigned int*)mask);
    ef_kernel<<<(Vn * Vn + 255) / 256, 256>>>(ea, Ew, adj);
    convert_x_kernel<<<(Bn * Vn * Dn / 4) / 256, 256>>>(x);
    convert_w_kernel<<<(Dn * Dn / 4) / 256, 256>>>(W);
    gemm_wx_kernel<<<dim3((Bn * Vn) / G_BM, Dn / G_BN), 256>>>();
    gat_attn_kernel<<<dim3(Hn, Bn), 256, ATT_SMEM_BYTES>>>(mask, a, out);
}

// round 7
// speedup vs baseline: 1.6500x; 1.1540x over previous
#include <cuda_runtime.h>
#include <cuda_bf16.h>
#include <math.h>
#include <stdint.h>

#define Bn 512
#define Vn 128
#define Dn 256
#define Hn 4
#define DHn 64

// ---------------- scratch (no cudaMalloc allowed) ----------------
__device__ __nv_bfloat16 g_xh[(size_t)Bn * Vn * Dn];   // x hi bf16
__device__ __nv_bfloat16 g_xl[(size_t)Bn * Vn * Dn];   // x lo bf16
__device__ __nv_bfloat16 g_Wh[Dn * Dn];                // W hi
__device__ __nv_bfloat16 g_Wl[Dn * Dn];                // W lo
__device__ __nv_bfloat16 g_Wxh[(size_t)Bn * Vn * Dn];  // Wx hi
__device__ __nv_bfloat16 g_Wxl[(size_t)Bn * Vn * Dn];  // Wx lo
__device__ float g_efm[Hn * Vn * Vn];                  // TRANSPOSED: [h][j][i] = adj? ef : -1e30
__device__ int   g_mask_mode;                          // 0=u8, 1=i32, 2=f32

#define NEGBIG (-1e30f)

// ---------------- helpers ----------------
__device__ __forceinline__ void mma_bf16(float* c, const uint32_t* a, uint32_t b0, uint32_t b1) {
    asm volatile(
        "mma.sync.aligned.m16n8k16.row.col.f32.bf16.bf16.f32 "
        "{%0,%1,%2,%3},{%4,%5,%6,%7},{%8,%9},{%0,%1,%2,%3};"
        : "+f"(c[0]), "+f"(c[1]), "+f"(c[2]), "+f"(c[3])
        : "r"(a[0]), "r"(a[1]), "r"(a[2]), "r"(a[3]), "r"(b0), "r"(b1));
}

__device__ __forceinline__ void ldsm_x4(uint32_t& r0, uint32_t& r1, uint32_t& r2, uint32_t& r3,
                                        uint32_t addr) {
    asm volatile("ldmatrix.sync.aligned.m8n8.x4.shared.b16 {%0,%1,%2,%3}, [%4];"
                 : "=r"(r0), "=r"(r1), "=r"(r2), "=r"(r3) : "r"(addr));
}
__device__ __forceinline__ void ldsm_x4_t(uint32_t& r0, uint32_t& r1, uint32_t& r2, uint32_t& r3,
                                          uint32_t addr) {
    asm volatile("ldmatrix.sync.aligned.m8n8.x4.trans.shared.b16 {%0,%1,%2,%3}, [%4];"
                 : "=r"(r0), "=r"(r1), "=r"(r2), "=r"(r3) : "r"(addr));
}
__device__ __forceinline__ uint32_t sptr(const void* p) {
    return (uint32_t)__cvta_generic_to_shared(p);
}

// split two floats into packed hi-pair and lo-pair bf16x2
__device__ __forceinline__ void split2(float a, float b, uint32_t& hi, uint32_t& lo) {
    __nv_bfloat16 ha = __float2bfloat16_rn(a);
    __nv_bfloat16 hb = __float2bfloat16_rn(b);
    float ra = a - __bfloat162float(ha);
    float rb = b - __bfloat162float(hb);
    __nv_bfloat162 vh; vh.x = ha; vh.y = hb;
    __nv_bfloat162 vl; vl.x = __float2bfloat16_rn(ra); vl.y = __float2bfloat16_rn(rb);
    hi = *reinterpret_cast<uint32_t*>(&vh);
    lo = *reinterpret_cast<uint32_t*>(&vl);
}

__device__ __forceinline__ float lrelu(float s) { return (s >= 0.f) ? s : 0.2f * s; }

// ---------------- mask dtype detection ----------------
__global__ void detect_mask_kernel(const unsigned int* __restrict__ m) {
    __shared__ int okInt, okFloat;
    if (threadIdx.x == 0) { okInt = 1; okFloat = 1; }
    __syncthreads();
    int badI = 0, badF = 0;
    for (int idx = threadIdx.x; idx < 16384; idx += 256) {
        unsigned int v = m[idx];
        if (v > 1u) badI = 1;
        if (v != 0u && v != 0x3f800000u) badF = 1;
    }
    if (badI) okInt = 0;
    if (badF) okFloat = 0;
    __syncthreads();
    if (threadIdx.x == 0) g_mask_mode = okFloat ? 2 : (okInt ? 1 : 0);
}

// ---------------- converts ----------------
__global__ __launch_bounds__(256) void convert_x_kernel(const float* __restrict__ x) {
    int gid = blockIdx.x * 256 + threadIdx.x;
    float4 v = ((const float4*)x)[gid];
    uint32_t h01, l01, h23, l23;
    split2(v.x, v.y, h01, l01);
    split2(v.z, v.w, h23, l23);
    ((uint2*)g_xh)[gid] = make_uint2(h01, h23);
    ((uint2*)g_xl)[gid] = make_uint2(l01, l23);
}

__global__ __launch_bounds__(256) void convert_w_kernel(const float* __restrict__ W) {
    int gid = blockIdx.x * 256 + threadIdx.x;
    float4 v = ((const float4*)W)[gid];
    uint32_t h01, l01, h23, l23;
    split2(v.x, v.y, h01, l01);
    split2(v.z, v.w, h23, l23);
    ((uint2*)g_Wh)[gid] = make_uint2(h01, h23);
    ((uint2*)g_Wl)[gid] = make_uint2(l01, l23);
}

// ---------------- efm[h][j][i] = adj[i][j] ? ea[i][j]·Ew[h] : -1e30 (transposed) --------
__global__ void ef_kernel(const float* __restrict__ ea, const float* __restrict__ Ew,
                          const int* __restrict__ adj) {
    int idx = blockIdx.x * blockDim.x + threadIdx.x;  // i*128+j
    if (idx >= Vn * Vn) return;
    float e0 = ea[idx * 2], e1 = ea[idx * 2 + 1];
    bool ok = adj[idx] != 0;
    int i = idx >> 7, j = idx & 127;
    int tidx = j * Vn + i;  // transposed
    g_efm[0 * 16384 + tidx] = ok ? (e0 * Ew[0] + e1 * Ew[1]) : NEGBIG;
    g_efm[1 * 16384 + tidx] = ok ? (e0 * Ew[2] + e1 * Ew[3]) : NEGBIG;
    g_efm[2 * 16384 + tidx] = ok ? (e0 * Ew[4] + e1 * Ew[5]) : NEGBIG;
    g_efm[3 * 16384 + tidx] = ok ? (e0 * Ew[6] + e1 * Ew[7]) : NEGBIG;
}

// ---------------- GEMM1: Wx = x @ W^T (3x bf16 split, ldmatrix) ----------------
#define G_BM 128
#define G_BN 64
#define G_BK 32
#define G_KP 40

__global__ __launch_bounds__(256) void gemm_wx_kernel() {
    __shared__ __nv_bfloat16 sAh[G_BM * G_KP];
    __shared__ __nv_bfloat16 sAl[G_BM * G_KP];
    __shared__ __nv_bfloat16 sBh[G_BN * G_KP];
    __shared__ __nv_bfloat16 sBl[G_BN * G_KP];

    int m0 = blockIdx.x * G_BM;
    int n0 = blockIdx.y * G_BN;
    int t = threadIdx.x;
    int w = t >> 5, lane = t & 31;
    int wm = w & 3;
    int wn = w >> 2;

    const uint32_t* gxh = (const uint32_t*)g_xh;
    const uint32_t* gxl = (const uint32_t*)g_xl;
    const uint32_t* gwh = (const uint32_t*)g_Wh;
    const uint32_t* gwl = (const uint32_t*)g_Wl;
    uint32_t* sAh32 = (uint32_t*)sAh;
    uint32_t* sAl32 = (uint32_t*)sAl;
    uint32_t* sBh32 = (uint32_t*)sBh;
    uint32_t* sBl32 = (uint32_t*)sBl;

    int rowoffA = ((lane >> 3) & 1) * 8 + (lane & 7);
    int coloffA = (lane >> 4) * 8;
    int rowoffB = (lane >> 4) * 8 + (lane & 7);
    int coloffB = ((lane >> 3) & 1) * 8;

    uint32_t aAh = sptr(sAh), aAl = sptr(sAl), aBh = sptr(sBh), aBl = sptr(sBl);

    float acc[2][4][4];
#pragma unroll
    for (int mt = 0; mt < 2; mt++)
#pragma unroll
        for (int nt = 0; nt < 4; nt++)
#pragma unroll
            for (int r = 0; r < 4; r++) acc[mt][nt][r] = 0.f;

    for (int k0 = 0; k0 < Dn; k0 += G_BK) {
#pragma unroll
        for (int q = 0; q < 8; q++) {
            int lin = t + 256 * q;
            int row = lin >> 4, cw = lin & 15;
            size_t src = (size_t)(m0 + row) * (Dn / 2) + (k0 >> 1) + cw;
            sAh32[row * (G_KP / 2) + cw] = gxh[src];
            sAl32[row * (G_KP / 2) + cw] = gxl[src];
        }
#pragma unroll
        for (int q = 0; q < 4; q++) {
            int lin = t + 256 * q;
            int row = lin >> 4, cw = lin & 15;
            size_t src = (size_t)(n0 + row) * (Dn / 2) + (k0 >> 1) + cw;
            sBh32[row * (G_KP / 2) + cw] = gwh[src];
            sBl32[row * (G_KP / 2) + cw] = gwl[src];
        }
        __syncthreads();

#pragma unroll
        for (int ks = 0; ks < G_BK; ks += 16) {
            uint32_t Ah[2][4], Al[2][4];
#pragma unroll
            for (int mt = 0; mt < 2; mt++) {
                uint32_t off = ((wm * 32 + mt * 16 + rowoffA) * G_KP + ks + coloffA) * 2;
                ldsm_x4(Ah[mt][0], Ah[mt][1], Ah[mt][2], Ah[mt][3], aAh + off);
                ldsm_x4(Al[mt][0], Al[mt][1], Al[mt][2], Al[mt][3], aAl + off);
            }
#pragma unroll
            for (int nc = 0; nc < 2; nc++) {
                uint32_t off = ((wn * 32 + nc * 16 + rowoffB) * G_KP + ks + coloffB) * 2;
                uint32_t bh0, bh1, bh2, bh3, bl0, bl1, bl2, bl3;
                ldsm_x4(bh0, bh1, bh2, bh3, aBh + off);
                ldsm_x4(bl0, bl1, bl2, bl3, aBl + off);
#pragma unroll
                for (int mt = 0; mt < 2; mt++) {
                    mma_bf16(acc[mt][nc * 2], Ah[mt], bh0, bh1);
                    mma_bf16(acc[mt][nc * 2], Al[mt], bh0, bh1);
                    mma_bf16(acc[mt][nc * 2], Ah[mt], bl0, bl1);
                    mma_bf16(acc[mt][nc * 2 + 1], Ah[mt], bh2, bh3);
                    mma_bf16(acc[mt][nc * 2 + 1], Al[mt], bh2, bh3);
                    mma_bf16(acc[mt][nc * 2 + 1], Ah[mt], bl2, bl3);
                }
            }
        }
        __syncthreads();
    }

#pragma unroll
    for (int mt = 0; mt < 2; mt++)
#pragma unroll
        for (int nt = 0; nt < 4; nt++) {
            int row0 = m0 + wm * 32 + mt * 16 + (lane >> 2);
            int col = n0 + wn * 32 + nt * 8 + (lane & 3) * 2;
            uint32_t hi, lo;
            split2(acc[mt][nt][0], acc[mt][nt][1], hi, lo);
            *(uint32_t*)&g_Wxh[(size_t)row0 * Dn + col] = hi;
            *(uint32_t*)&g_Wxl[(size_t)row0 * Dn + col] = lo;
            split2(acc[mt][nt][2], acc[mt][nt][3], hi, lo);
            *(uint32_t*)&g_Wxh[(size_t)(row0 + 8) * Dn + col] = hi;
            *(uint32_t*)&g_Wxl[(size_t)(row0 + 8) * Dn + col] = lo;
        }
}

// ---------------- fused attention per (b, h) ----------------
#define WSTR 72  // W row stride (bf16): 36 words -> conflict-free ldmatrix
// SMEM: sWh 18432 | sWl 18432 | misc 4096 = 40960 B
#define ATT_SMEM_BYTES 40960

__global__ __launch_bounds__(256, 2) void gat_attn_kernel(const void* __restrict__ maskp,
                                                          const float* __restrict__ a,
                                                          float* __restrict__ out) {
    extern __shared__ char smem[];
    __nv_bfloat16* sWh = (__nv_bfloat16*)smem;
    __nv_bfloat16* sWl = (__nv_bfloat16*)(smem + 18432);
    float* sAvec = (float*)(smem + 36864);  // 128
    float* sMb = sAvec + 128;               // 128
    float* sSrc = sAvec + 256;              // 128
    float* sDst = sAvec + 384;              // 128
    float* sPS = sAvec + 512;               // 256
    float* sPD = sAvec + 768;               // 256

    int h = blockIdx.x;
    int b = blockIdx.y;
    int t = threadIdx.x;

    if (t < 128) {
        sAvec[t] = a[t];
        int mode = g_mask_mode;
        bool mv;
        int idx = b * Vn + t;
        if (mode == 0)      mv = ((const unsigned char*)maskp)[idx] != 0;
        else if (mode == 1) mv = ((const int*)maskp)[idx] != 0;
        else                mv = ((const float*)maskp)[idx] != 0.f;
        sMb[t] = mv ? NEGBIG : 0.f;
    }
    __syncthreads();

    // ---- load Wx[b,:,h,:] hi/lo into sW [i][d] + partial a-dots ----
    {
        int i = t >> 1, half = t & 1;
        size_t base = ((size_t)(b * Vn + i) * Dn + h * DHn) >> 1;  // u32 units
        const uint32_t* ph = (const uint32_t*)g_Wxh + base + half * 16;
        const uint32_t* pl = (const uint32_t*)g_Wxl + base + half * 16;
        uint32_t* wh32 = (uint32_t*)sWh;
        uint32_t* wl32 = (uint32_t*)sWl;
        float ss = 0.f, sd = 0.f;
#pragma unroll
        for (int q = 0; q < 16; q++) {
            uint32_t uh = ph[q], ul = pl[q];
            int d = half * 32 + q * 2;
            wh32[i * (WSTR / 2) + (d >> 1)] = uh;
            wl32[i * (WSTR / 2) + (d >> 1)] = ul;
            float2 fh = __bfloat1622float2(*(__nv_bfloat162*)&uh);
            float2 fl = __bfloat1622float2(*(__nv_bfloat162*)&ul);
            float f0 = fh.x + fl.x, f1 = fh.y + fl.y;
            ss += f0 * sAvec[d] + f1 * sAvec[d + 1];
            sd += f0 * sAvec[64 + d] + f1 * sAvec[64 + d + 1];
        }
        sPS[t] = ss;
        sPD[t] = sd;
    }
    __syncthreads();
    if (t < 128) {
        sSrc[t] = sPS[2 * t] + sPS[2 * t + 1] + sMb[t];
        sDst[t] = sPD[2 * t] + sPD[2 * t + 1] + sMb[t];
    }
    __syncthreads();

    // ---- scores in MMA A-fragment layout: lane owns rows j0=(w*16+q), j1=j0+8 ----
    int w = t >> 5, lane = t & 31;
    int q = lane >> 2, cpos = (lane & 3) * 2;
    int j0 = w * 16 + q;
    int j1 = j0 + 8;

    const float* efT = g_efm + h * (Vn * Vn);
    float dst0 = sDst[j0], dst1 = sDst[j1];

    // ev[r][k0*4 + {0: i=c, 1: i=c+1, 2: i=c+8, 3: i=c+9}] where c = 16*k0 + cpos
    float ev0[32], ev1[32];
    float mx0 = NEGBIG * 4.f, mx1 = NEGBIG * 4.f;
#pragma unroll
    for (int k0 = 0; k0 < 8; k0++) {
        int ib = k0 * 16 + cpos;
        float2 sA = *(const float2*)&sSrc[ib];
        float2 sB = *(const float2*)&sSrc[ib + 8];
        float2 eA0 = *(const float2*)&efT[j0 * Vn + ib];
        float2 eB0 = *(const float2*)&efT[j0 * Vn + ib + 8];
        float2 eA1 = *(const float2*)&efT[j1 * Vn + ib];
        float2 eB1 = *(const float2*)&efT[j1 * Vn + ib + 8];
        float v;
        v = lrelu(sA.x + dst0 + eA0.x); ev0[k0 * 4 + 0] = v; mx0 = fmaxf(mx0, v);
        v = lrelu(sA.y + dst0 + eA0.y); ev0[k0 * 4 + 1] = v; mx0 = fmaxf(mx0, v);
        v = lrelu(sB.x + dst0 + eB0.x); ev0[k0 * 4 + 2] = v; mx0 = fmaxf(mx0, v);
        v = lrelu(sB.y + dst0 + eB0.y); ev0[k0 * 4 + 3] = v; mx0 = fmaxf(mx0, v);
        v = lrelu(sA.x + dst1 + eA1.x); ev1[k0 * 4 + 0] = v; mx1 = fmaxf(mx1, v);
        v = lrelu(sA.y + dst1 + eA1.y); ev1[k0 * 4 + 1] = v; mx1 = fmaxf(mx1, v);
        v = lrelu(sB.x + dst1 + eB1.x); ev1[k0 * 4 + 2] = v; mx1 = fmaxf(mx1, v);
        v = lrelu(sB.y + dst1 + eB1.y); ev1[k0 * 4 + 3] = v; mx1 = fmaxf(mx1, v);
    }
    // quad reduce max (lanes 4q..4q+3 cover all 128 i of rows j0/j1)
    mx0 = fmaxf(mx0, __shfl_xor_sync(0xffffffffu, mx0, 1));
    mx0 = fmaxf(mx0, __shfl_xor_sync(0xffffffffu, mx0, 2));
    mx1 = fmaxf(mx1, __shfl_xor_sync(0xffffffffu, mx1, 1));
    mx1 = fmaxf(mx1, __shfl_xor_sync(0xffffffffu, mx1, 2));

    // ---- exp, pack, and aggregate (fused so ev dies progressively) ----
    int rowoffBt = ((lane >> 3) & 1) * 8 + (lane & 7);
    int coloffBt = (lane >> 4) * 8;
    uint32_t aWh = sptr(sWh), aWl = sptr(sWl);

    float acc[8][4];
#pragma unroll
    for (int nt = 0; nt < 8; nt++)
#pragma unroll
        for (int r = 0; r < 4; r++) acc[nt][r] = 0.f;

    float s0 = 0.f, s1 = 0.f;
#pragma unroll
    for (int k0 = 0; k0 < 8; k0++) {
        float p00 = __expf(ev0[k0 * 4 + 0] - mx0);
        float p01 = __expf(ev0[k0 * 4 + 1] - mx0);
        float p02 = __expf(ev0[k0 * 4 + 2] - mx0);
        float p03 = __expf(ev0[k0 * 4 + 3] - mx0);
        float p10 = __expf(ev1[k0 * 4 + 0] - mx1);
        float p11 = __expf(ev1[k0 * 4 + 1] - mx1);
        float p12 = __expf(ev1[k0 * 4 + 2] - mx1);
        float p13 = __expf(ev1[k0 * 4 + 3] - mx1);
        s0 += p00 + p01 + p02 + p03;
        s1 += p10 + p11 + p12 + p13;
        uint32_t Ah[4], Al[4];
        split2(p00, p01, Ah[0], Al[0]);  // a0: row j0, k low pair
        split2(p10, p11, Ah[1], Al[1]);  // a1: row j1, k low pair
        split2(p02, p03, Ah[2], Al[2]);  // a2: row j0, k high pair
        split2(p12, p13, Ah[3], Al[3]);  // a3: row j1, k high pair
#pragma unroll
        for (int nc = 0; nc < 4; nc++) {
            uint32_t offB = ((k0 * 16 + rowoffBt) * WSTR + nc * 16 + coloffBt) * 2;
            uint32_t bh0, bh1, bh2, bh3, bl0, bl1, bl2, bl3;
            ldsm_x4_t(bh0, bh1, bh2, bh3, aWh + offB);
            ldsm_x4_t(bl0, bl1, bl2, bl3, aWl + offB);
            mma_bf16(acc[nc * 2], Ah, bh0, bh1);
            mma_bf16(acc[nc * 2], Al, bh0, bh1);
            mma_bf16(acc[nc * 2], Ah, bl0, bl1);
            mma_bf16(acc[nc * 2 + 1], Ah, bh2, bh3);
            mma_bf16(acc[nc * 2 + 1], Al, bh2, bh3);
            mma_bf16(acc[nc * 2 + 1], Ah, bl2, bl3);
        }
    }
    // quad reduce denom
    s0 += __shfl_xor_sync(0xffffffffu, s0, 1);
    s0 += __shfl_xor_sync(0xffffffffu, s0, 2);
    s1 += __shfl_xor_sync(0xffffffffu, s1, 1);
    s1 += __shfl_xor_sync(0xffffffffu, s1, 2);
    float inv0 = 1.0f / s0;  // s >= 1 always (max element contributes exp(0)=1)
    float inv1 = 1.0f / s1;

    // ---- epilogue: normalize, ELU, mask, store ----
    bool msk0 = (sMb[j0] != 0.f);
    bool msk1 = (sMb[j1] != 0.f);
#pragma unroll
    for (int nt = 0; nt < 8; nt++) {
        int dd = nt * 8 + cpos;
        {
            float v0 = acc[nt][0] * inv0;
            float v1 = acc[nt][1] * inv0;
            float2 o;
            o.x = msk0 ? 0.f : (v0 > 0.f ? v0 : expm1f(v0));
            o.y = msk0 ? 0.f : (v1 > 0.f ? v1 : expm1f(v1));
            *(float2*)(out + (size_t)(b * Vn + j0) * Dn + h * DHn + dd) = o;
        }
        {
            float v0 = acc[nt][2] * inv1;
            float v1 = acc[nt][3] * inv1;
            float2 o;
            o.x = msk1 ? 0.f : (v0 > 0.f ? v0 : expm1f(v0));
            o.y = msk1 ? 0.f : (v1 > 0.f ? v1 : expm1f(v1));
            *(float2*)(out + (size_t)(b * Vn + j1) * Dn + h * DHn + dd) = o;
        }
    }
}

// ---------------- launch ----------------
extern "C" void kernel_launch(void* const* d_in, const int* in_sizes, int n_in,
                              void* d_out, int out_size) {
    const float* x    = (const float*)d_in[0];
    const int*   adj  = (const int*)d_in[1];
    const float* ea   = (const float*)d_in[2];
    const void*  mask = (const void*)d_in[3];
    const float* W    = (const float*)d_in[4];
    const float* a    = (const float*)d_in[5];
    const float* Ew   = (const float*)d_in[6];
    float* out = (float*)d_out;

    cudaFuncSetAttribute(gat_attn_kernel, cudaFuncAttributeMaxDynamicSharedMemorySize,
                         ATT_SMEM_BYTES);

    detect_mask_kernel<<<1, 256>>>((const unsigned int*)mask);
    ef_kernel<<<(Vn * Vn + 255) / 256, 256>>>(ea, Ew, adj);
    convert_x_kernel<<<(Bn * Vn * Dn / 4) / 256, 256>>>(x);
    convert_w_kernel<<<(Dn * Dn / 4) / 256, 256>>>(W);
    gemm_wx_kernel<<<dim3((Bn * Vn) / G_BM, Dn / G_BN), 256>>>();
    gat_attn_kernel<<<dim3(Hn, Bn), 256, ATT_SMEM_BYTES>>>(mask, a, out);
}

// round 9
// speedup vs baseline: 1.9319x; 1.1708x over previous
#include <cuda_runtime.h>
#include <cuda_bf16.h>
#include <math.h>
#include <stdint.h>

#define Bn 512
#define Vn 128
#define Dn 256
#define Hn 4
#define DHn 64

// ---------------- scratch (no cudaMalloc allowed) ----------------
__device__ __nv_bfloat16 g_Wh[Dn * Dn];                // W hi
__device__ __nv_bfloat16 g_Wl[Dn * Dn];                // W lo
__device__ __nv_bfloat16 g_Wxh[(size_t)Bn * Vn * Dn];  // Wx hi
__device__ __nv_bfloat16 g_Wxl[(size_t)Bn * Vn * Dn];  // Wx lo
__device__ float g_efm[Hn * Vn * Vn];                  // TRANSPOSED: [h][j][i] = adj? ef : -1e30
__device__ float g_efmax[Hn * Vn];                     // [h][j] = max_i efm
__device__ int   g_mask_mode;                          // 0=u8, 1=i32, 2=f32

#define NEGBIG (-1e30f)

// ---------------- helpers ----------------
__device__ __forceinline__ void mma_bf16(float* c, const uint32_t* a, uint32_t b0, uint32_t b1) {
    asm volatile(
        "mma.sync.aligned.m16n8k16.row.col.f32.bf16.bf16.f32 "
        "{%0,%1,%2,%3},{%4,%5,%6,%7},{%8,%9},{%0,%1,%2,%3};"
        : "+f"(c[0]), "+f"(c[1]), "+f"(c[2]), "+f"(c[3])
        : "r"(a[0]), "r"(a[1]), "r"(a[2]), "r"(a[3]), "r"(b0), "r"(b1));
}

__device__ __forceinline__ void ldsm_x4(uint32_t& r0, uint32_t& r1, uint32_t& r2, uint32_t& r3,
                                        uint32_t addr) {
    asm volatile("ldmatrix.sync.aligned.m8n8.x4.shared.b16 {%0,%1,%2,%3}, [%4];"
                 : "=r"(r0), "=r"(r1), "=r"(r2), "=r"(r3) : "r"(addr));
}
__device__ __forceinline__ void ldsm_x4_t(uint32_t& r0, uint32_t& r1, uint32_t& r2, uint32_t& r3,
                                          uint32_t addr) {
    asm volatile("ldmatrix.sync.aligned.m8n8.x4.trans.shared.b16 {%0,%1,%2,%3}, [%4];"
                 : "=r"(r0), "=r"(r1), "=r"(r2), "=r"(r3) : "r"(addr));
}
__device__ __forceinline__ uint32_t sptr(const void* p) {
    return (uint32_t)__cvta_generic_to_shared(p);
}

__device__ __forceinline__ void split2(float a, float b, uint32_t& hi, uint32_t& lo) {
    __nv_bfloat16 ha = __float2bfloat16_rn(a);
    __nv_bfloat16 hb = __float2bfloat16_rn(b);
    float ra = a - __bfloat162float(ha);
    float rb = b - __bfloat162float(hb);
    __nv_bfloat162 vh; vh.x = ha; vh.y = hb;
    __nv_bfloat162 vl; vl.x = __float2bfloat16_rn(ra); vl.y = __float2bfloat16_rn(rb);
    hi = *reinterpret_cast<uint32_t*>(&vh);
    lo = *reinterpret_cast<uint32_t*>(&vl);
}

__device__ __forceinline__ float lrelu(float s) { return (s >= 0.f) ? s : 0.2f * s; }

// ---------------- mask dtype detection ----------------
__global__ void detect_mask_kernel(const unsigned int* __restrict__ m) {
    __shared__ int okInt, okFloat;
    if (threadIdx.x == 0) { okInt = 1; okFloat = 1; }
    __syncthreads();
    int badI = 0, badF = 0;
    for (int idx = threadIdx.x; idx < 16384; idx += 256) {
        unsigned int v = m[idx];
        if (v > 1u) badI = 1;
        if (v != 0u && v != 0x3f800000u) badF = 1;
    }
    if (badI) okInt = 0;
    if (badF) okFloat = 0;
    __syncthreads();
    if (threadIdx.x == 0) g_mask_mode = okFloat ? 2 : (okInt ? 1 : 0);
}

// ---------------- W convert ----------------
__global__ __launch_bounds__(256) void convert_w_kernel(const float* __restrict__ W) {
    int gid = blockIdx.x * 256 + threadIdx.x;
    float4 v = ((const float4*)W)[gid];
    uint32_t h01, l01, h23, l23;
    split2(v.x, v.y, h01, l01);
    split2(v.z, v.w, h23, l23);
    ((uint2*)g_Wh)[gid] = make_uint2(h01, h23);
    ((uint2*)g_Wl)[gid] = make_uint2(l01, l23);
}

// ---------------- efm[h][j][i] (transposed) ----------------
__global__ void ef_kernel(const float* __restrict__ ea, const float* __restrict__ Ew,
                          const int* __restrict__ adj) {
    int idx = blockIdx.x * blockDim.x + threadIdx.x;  // i*128+j
    if (idx >= Vn * Vn) return;
    float e0 = ea[idx * 2], e1 = ea[idx * 2 + 1];
    bool ok = adj[idx] != 0;
    int i = idx >> 7, j = idx & 127;
    int tidx = j * Vn + i;
    g_efm[0 * 16384 + tidx] = ok ? (e0 * Ew[0] + e1 * Ew[1]) : NEGBIG;
    g_efm[1 * 16384 + tidx] = ok ? (e0 * Ew[2] + e1 * Ew[3]) : NEGBIG;
    g_efm[2 * 16384 + tidx] = ok ? (e0 * Ew[4] + e1 * Ew[5]) : NEGBIG;
    g_efm[3 * 16384 + tidx] = ok ? (e0 * Ew[6] + e1 * Ew[7]) : NEGBIG;
}

// ---------------- efmax[h][j] = max_i efm[h][j][i] ----------------
__global__ void efmax_kernel() {
    int h = blockIdx.x, j = threadIdx.x;
    const float4* row = (const float4*)(g_efm + h * 16384 + j * Vn);
    float m = -4e30f;
#pragma unroll 8
    for (int q = 0; q < 32; q++) {
        float4 v = row[q];
        m = fmaxf(m, fmaxf(fmaxf(v.x, v.y), fmaxf(v.z, v.w)));
    }
    g_efmax[h * Vn + j] = m;
}

// ---------------- GEMM1: Wx = x @ W^T, BM=128 BN=256 BK=32, 512 thr ----------------
// SMEM stage: Ah 10240 | Al 10240 | Bh 20480 | Bl 20480 = 61440; x2 stages
#define GSTAGE 61440
#define GEMM_SMEM (2 * GSTAGE)

__global__ __launch_bounds__(512) void gemm_wx_kernel(const float* __restrict__ x) {
    extern __shared__ char gs[];
    int m0 = blockIdx.x * 128;
    int t = threadIdx.x;
    int w = t >> 5, lane = t & 31;
    int wm = w & 3, wn = w >> 2;  // warp tile: 32m x 64n

    int rowoffA = ((lane >> 3) & 1) * 8 + (lane & 7);
    int coloffA = (lane >> 4) * 8;
    int rowoffB = (lane >> 4) * 8 + (lane & 7);
    int coloffB = ((lane >> 3) & 1) * 8;

    const uint4* gwh4 = (const uint4*)g_Wh;
    const uint4* gwl4 = (const uint4*)g_Wl;

    int arow0 = t >> 3, acq0 = t & 7;
    int arow1 = arow0 + 64;
    int brow0 = t >> 1, bhalf = t & 1;  // 512 threads cover 256 B rows x 2 halves

    float4 ax0, ax1;
    uint4 rbh0, rbh1, rbl0, rbl1;

    float acc[2][8][4];
#pragma unroll
    for (int mt = 0; mt < 2; mt++)
#pragma unroll
        for (int nt = 0; nt < 8; nt++)
#pragma unroll
            for (int r = 0; r < 4; r++) acc[mt][nt][r] = 0.f;

#define G_LDG(k0)                                                                     \
    do {                                                                              \
        ax0 = *(const float4*)(x + (size_t)(m0 + arow0) * Dn + (k0) + acq0 * 4);      \
        ax1 = *(const float4*)(x + (size_t)(m0 + arow1) * Dn + (k0) + acq0 * 4);      \
        int bi0 = (brow0 * (Dn / 2) + ((k0) >> 1) + bhalf * 8) >> 2;                  \
        rbh0 = gwh4[bi0]; rbh1 = gwh4[bi0 + 1];                                       \
        rbl0 = gwl4[bi0]; rbl1 = gwl4[bi0 + 1];                                       \
    } while (0)

#define G_STS(s)                                                                      \
    do {                                                                              \
        char* st = gs + (s) * GSTAGE;                                                 \
        uint32_t* ah = (uint32_t*)st;                                                 \
        uint32_t* al = (uint32_t*)(st + 10240);                                       \
        uint4* bh = (uint4*)(st + 20480);                                             \
        uint4* bl = (uint4*)(st + 40960);                                             \
        uint32_t h01, l01, h23, l23;                                                  \
        split2(ax0.x, ax0.y, h01, l01); split2(ax0.z, ax0.w, h23, l23);               \
        ah[arow0 * 20 + acq0 * 2] = h01; ah[arow0 * 20 + acq0 * 2 + 1] = h23;         \
        al[arow0 * 20 + acq0 * 2] = l01; al[arow0 * 20 + acq0 * 2 + 1] = l23;         \
        split2(ax1.x, ax1.y, h01, l01); split2(ax1.z, ax1.w, h23, l23);               \
        ah[arow1 * 20 + acq0 * 2] = h01; ah[arow1 * 20 + acq0 * 2 + 1] = h23;         \
        al[arow1 * 20 + acq0 * 2] = l01; al[arow1 * 20 + acq0 * 2 + 1] = l23;         \
        bh[brow0 * 5 + bhalf * 2] = rbh0; bh[brow0 * 5 + bhalf * 2 + 1] = rbh1;       \
        bl[brow0 * 5 + bhalf * 2] = rbl0; bl[brow0 * 5 + bhalf * 2 + 1] = rbl1;       \
    } while (0)

    G_LDG(0);
    G_STS(0);
    G_LDG(32);
    __syncthreads();

    for (int ki = 0; ki < 8; ki++) {
        char* st = gs + (ki & 1) * GSTAGE;
        uint32_t aAh = sptr(st), aAl = sptr(st + 10240);
        uint32_t aBh = sptr(st + 20480), aBl = sptr(st + 40960);
#pragma unroll
        for (int ks = 0; ks < 32; ks += 16) {
            uint32_t Ah[2][4], Al[2][4];
#pragma unroll
            for (int mt = 0; mt < 2; mt++) {
                uint32_t off = (wm * 32 + mt * 16 + rowoffA) * 80 + (ks + coloffA) * 2;
                ldsm_x4(Ah[mt][0], Ah[mt][1], Ah[mt][2], Ah[mt][3], aAh + off);
                ldsm_x4(Al[mt][0], Al[mt][1], Al[mt][2], Al[mt][3], aAl + off);
            }
#pragma unroll
            for (int nb = 0; nb < 4; nb++) {
                uint32_t off = (wn * 64 + nb * 16 + rowoffB) * 80 + (ks + coloffB) * 2;
                uint32_t bh0, bh1, bh2, bh3, bl0, bl1, bl2, bl3;
                ldsm_x4(bh0, bh1, bh2, bh3, aBh + off);
                ldsm_x4(bl0, bl1, bl2, bl3, aBl + off);
#pragma unroll
                for (int mt = 0; mt < 2; mt++) {
                    mma_bf16(acc[mt][nb * 2], Ah[mt], bh0, bh1);
                    mma_bf16(acc[mt][nb * 2], Al[mt], bh0, bh1);
                    mma_bf16(acc[mt][nb * 2], Ah[mt], bl0, bl1);
                    mma_bf16(acc[mt][nb * 2 + 1], Ah[mt], bh2, bh3);
                    mma_bf16(acc[mt][nb * 2 + 1], Al[mt], bh2, bh3);
                    mma_bf16(acc[mt][nb * 2 + 1], Ah[mt], bl2, bl3);
                }
            }
        }
        __syncthreads();
        if (ki < 7) {
            G_STS((ki + 1) & 1);
            if (ki < 6) G_LDG((ki + 2) * 32);
            __syncthreads();
        }
    }

#pragma unroll
    for (int mt = 0; mt < 2; mt++)
#pragma unroll
        for (int nt = 0; nt < 8; nt++) {
            int row0 = m0 + wm * 32 + mt * 16 + (lane >> 2);
            int col = wn * 64 + nt * 8 + (lane & 3) * 2;
            uint32_t hi, lo;
            split2(acc[mt][nt][0], acc[mt][nt][1], hi, lo);
            *(uint32_t*)&g_Wxh[(size_t)row0 * Dn + col] = hi;
            *(uint32_t*)&g_Wxl[(size_t)row0 * Dn + col] = lo;
            split2(acc[mt][nt][2], acc[mt][nt][3], hi, lo);
            *(uint32_t*)&g_Wxh[(size_t)(row0 + 8) * Dn + col] = hi;
            *(uint32_t*)&g_Wxl[(size_t)(row0 + 8) * Dn + col] = lo;
        }
}

// ---------------- fused attention per (b, h) ----------------
#define WSTR 72  // bf16 stride -> conflict-free ldmatrix
// SMEM: sWh 18432 | sWl 18432 | misc
#define ATT_SMEM_BYTES 41088

__global__ __launch_bounds__(256, 2) void gat_attn_kernel(const void* __restrict__ maskp,
                                                          const float* __restrict__ a,
                                                          float* __restrict__ out) {
    extern __shared__ char smem[];
    __nv_bfloat16* sWh = (__nv_bfloat16*)smem;
    __nv_bfloat16* sWl = (__nv_bfloat16*)(smem + 18432);
    float* sAvec = (float*)(smem + 36864);  // 128
    float* sMb = sAvec + 128;               // 128
    float* sSrc = sAvec + 256;              // 128
    float* sDst = sAvec + 384;              // 128
    float* sPS = sAvec + 512;               // 256
    float* sPD = sAvec + 768;               // 256
    float* sMax = sAvec + 1024;             // 1

    int h = blockIdx.x;
    int b = blockIdx.y;
    int t = threadIdx.x;

    if (t < 128) {
        sAvec[t] = a[t];
        int mode = g_mask_mode;
        bool mv;
        int idx = b * Vn + t;
        if (mode == 0)      mv = ((const unsigned char*)maskp)[idx] != 0;
        else if (mode == 1) mv = ((const int*)maskp)[idx] != 0;
        else                mv = ((const float*)maskp)[idx] != 0.f;
        sMb[t] = mv ? NEGBIG : 0.f;
    }
    __syncthreads();

    // ---- load Wx[b,:,h,:] hi/lo into sW [i][d] + partial a-dots ----
    {
        int i = t >> 1, half = t & 1;
        size_t base32 = ((size_t)(b * Vn + i) * Dn + h * DHn) >> 1;
        const uint4* ph4 = (const uint4*)((const uint32_t*)g_Wxh + base32 + half * 16);
        const uint4* pl4 = (const uint4*)((const uint32_t*)g_Wxl + base32 + half * 16);
        uint4 h4[4], l4[4];
#pragma unroll
        for (int q = 0; q < 4; q++) { h4[q] = ph4[q]; l4[q] = pl4[q]; }
        uint32_t* wh32 = (uint32_t*)sWh;
        uint32_t* wl32 = (uint32_t*)sWl;
        const uint32_t* hh = (const uint32_t*)h4;
        const uint32_t* ll = (const uint32_t*)l4;
        float ss = 0.f, sd = 0.f;
#pragma unroll
        for (int q = 0; q < 16; q++) {
            uint32_t uh = hh[q], ul = ll[q];
            int d = half * 32 + q * 2;
            wh32[i * (WSTR / 2) + (d >> 1)] = uh;
            wl32[i * (WSTR / 2) + (d >> 1)] = ul;
            float2 fh = __bfloat1622float2(*(__nv_bfloat162*)&uh);
            float2 fl = __bfloat1622float2(*(__nv_bfloat162*)&ul);
            float f0 = fh.x + fl.x, f1 = fh.y + fl.y;
            ss += f0 * sAvec[d] + f1 * sAvec[d + 1];
            sd += f0 * sAvec[64 + d] + f1 * sAvec[64 + d + 1];
        }
        sPS[t] = ss;
        sPD[t] = sd;
    }
    __syncthreads();
    if (t < 128) {
        sSrc[t] = sPS[2 * t] + sPS[2 * t + 1] + sMb[t];
        sDst[t] = sPD[2 * t] + sPD[2 * t + 1] + sMb[t];
    }
    __syncthreads();
    if (t < 32) {
        float m = fmaxf(fmaxf(sSrc[t], sSrc[t + 32]), fmaxf(sSrc[t + 64], sSrc[t + 96]));
        m = fmaxf(m, __shfl_xor_sync(0xffffffffu, m, 1));
        m = fmaxf(m, __shfl_xor_sync(0xffffffffu, m, 2));
        m = fmaxf(m, __shfl_xor_sync(0xffffffffu, m, 4));
        m = fmaxf(m, __shfl_xor_sync(0xffffffffu, m, 8));
        m = fmaxf(m, __shfl_xor_sync(0xffffffffu, m, 16));
        if (t == 0) sMax[0] = m;
    }
    __syncthreads();

    // ---- single pass: scores -> p = exp(e - m_ub) -> mma, fragment-resident ----
    int w = t >> 5, lane = t & 31;
    int q = lane >> 2, cpos = (lane & 3) * 2;
    int j0 = w * 16 + q;
    int j1 = j0 + 8;

    const float* efT = g_efm + h * (Vn * Vn);
    float dst0 = sDst[j0], dst1 = sDst[j1];
    float maxSrcV = sMax[0];
    float m0v = lrelu(maxSrcV + dst0 + g_efmax[h * Vn + j0]);
    float m1v = lrelu(maxSrcV + dst1 + g_efmax[h * Vn + j1]);

    int rowoffBt = ((lane >> 3) & 1) * 8 + (lane & 7);
    int coloffBt = (lane >> 4) * 8;
    uint32_t aWh = sptr(sWh), aWl = sptr(sWl);

    float acc[8][4];
#pragma unroll
    for (int nt = 0; nt < 8; nt++)
#pragma unroll
        for (int r = 0; r < 4; r++) acc[nt][r] = 0.f;

    float s0 = 0.f, s1 = 0.f;
#pragma unroll
    for (int k0 = 0; k0 < 8; k0++) {
        int ib = k0 * 16 + cpos;
        float2 sA = *(const float2*)&sSrc[ib];
        float2 sB = *(const float2*)&sSrc[ib + 8];
        float2 eA0 = *(const float2*)&efT[j0 * Vn + ib];
        float2 eB0 = *(const float2*)&efT[j0 * Vn + ib + 8];
        float2 eA1 = *(const float2*)&efT[j1 * Vn + ib];
        float2 eB1 = *(const float2*)&efT[j1 * Vn + ib + 8];
        float p00 = __expf(lrelu(sA.x + dst0 + eA0.x) - m0v);
        float p01 = __expf(lrelu(sA.y + dst0 + eA0.y) - m0v);
        float p02 = __expf(lrelu(sB.x + dst0 + eB0.x) - m0v);
        float p03 = __expf(lrelu(sB.y + dst0 + eB0.y) - m0v);
        float p10 = __expf(lrelu(sA.x + dst1 + eA1.x) - m1v);
        float p11 = __expf(lrelu(sA.y + dst1 + eA1.y) - m1v);
        float p12 = __expf(lrelu(sB.x + dst1 + eB1.x) - m1v);
        float p13 = __expf(lrelu(sB.y + dst1 + eB1.y) - m1v);
        s0 += p00 + p01 + p02 + p03;
        s1 += p10 + p11 + p12 + p13;
        uint32_t Ah[4], Al[4];
        split2(p00, p01, Ah[0], Al[0]);
        split2(p10, p11, Ah[1], Al[1]);
        split2(p02, p03, Ah[2], Al[2]);
        split2(p12, p13, Ah[3], Al[3]);
#pragma unroll
        for (int nc = 0; nc < 4; nc++) {
            uint32_t offB = ((k0 * 16 + rowoffBt) * WSTR + nc * 16 + coloffBt) * 2;
            uint32_t bh0, bh1, bh2, bh3, bl0, bl1, bl2, bl3;
            ldsm_x4_t(bh0, bh1, bh2, bh3, aWh + offB);
            ldsm_x4_t(bl0, bl1, bl2, bl3, aWl + offB);
            mma_bf16(acc[nc * 2], Ah, bh0, bh1);
            mma_bf16(acc[nc * 2], Al, bh0, bh1);
            mma_bf16(acc[nc * 2], Ah, bl0, bl1);
            mma_bf16(acc[nc * 2 + 1], Ah, bh2, bh3);
            mma_bf16(acc[nc * 2 + 1], Al, bh2, bh3);
            mma_bf16(acc[nc * 2 + 1], Ah, bl2, bl3);
        }
    }
    s0 += __shfl_xor_sync(0xffffffffu, s0, 1);
    s0 += __shfl_xor_sync(0xffffffffu, s0, 2);
    s1 += __shfl_xor_sync(0xffffffffu, s1, 1);
    s1 += __shfl_xor_sync(0xffffffffu, s1, 2);
    float inv0 = 1.0f / s0;
    float inv1 = 1.0f / s1;

    bool msk0 = (sMb[j0] != 0.f);
    bool msk1 = (sMb[j1] != 0.f);
#pragma unroll
    for (int nt = 0; nt < 8; nt++) {
        int dd = nt * 8 + cpos;
        {
            float v0 = acc[nt][0] * inv0;
            float v1 = acc[nt][1] * inv0;
            float2 o;
            o.x = msk0 ? 0.f : (v0 > 0.f ? v0 : __expf(v0) - 1.f);
            o.y = msk0 ? 0.f : (v1 > 0.f ? v1 : __expf(v1) - 1.f);
            *(float2*)(out + (size_t)(b * Vn + j0) * Dn + h * DHn + dd) = o;
        }
        {
            float v0 = acc[nt][2] * inv1;
            float v1 = acc[nt][3] * inv1;
            float2 o;
            o.x = msk1 ? 0.f : (v0 > 0.f ? v0 : __expf(v0) - 1.f);
            o.y = msk1 ? 0.f : (v1 > 0.f ? v1 : __expf(v1) - 1.f);
            *(float2*)(out + (size_t)(b * Vn + j1) * Dn + h * DHn + dd) = o;
        }
    }
}

// ---------------- launch ----------------
extern "C" void kernel_launch(void* const* d_in, const int* in_sizes, int n_in,
                              void* d_out, int out_size) {
    const float* x    = (const float*)d_in[0];
    const int*   adj  = (const int*)d_in[1];
    const float* ea   = (const float*)d_in[2];
    const void*  mask = (const void*)d_in[3];
    const float* W    = (const float*)d_in[4];
    const float* a    = (const float*)d_in[5];
    const float* Ew   = (const float*)d_in[6];
    float* out = (float*)d_out;

    cudaFuncSetAttribute(gat_attn_kernel, cudaFuncAttributeMaxDynamicSharedMemorySize,
                         ATT_SMEM_BYTES);
    cudaFuncSetAttribute(gemm_wx_kernel, cudaFuncAttributeMaxDynamicSharedMemorySize,
                         GEMM_SMEM);

    detect_mask_kernel<<<1, 256>>>((const unsigned int*)mask);
    ef_kernel<<<(Vn * Vn + 255) / 256, 256>>>(ea, Ew, adj);
    efmax_kernel<<<Hn, Vn>>>();
    convert_w_kernel<<<(Dn * Dn / 4) / 256, 256>>>(W);
    gemm_wx_kernel<<<(Bn * Vn) / 128, 512, GEMM_SMEM>>>(x);
    gat_attn_kernel<<<dim3(Hn, Bn), 256, ATT_SMEM_BYTES>>>(mask, a, out);
}